// round 13
// baseline (speedup 1.0000x reference)
#include <cuda_runtime.h>
#include <cuda_bf16.h>
#include <cstdint>

// Problem constants
static constexpr int KN = 50000;   // nodes
static constexpr int KE = 150000;  // edges
// dims: IN=16, HID=32, LAT=16, EF=8, HE=128
static constexpr int PK = 136;     // bf16 pitch for [n][k] / [e][k] tiles

// ---------------- device scratch (static, no allocation) ----------------
__device__ __align__(16) float g_agg[KN * 32];
__device__ __align__(16) float g_h1[KN * 32];
__device__ __align__(16) float g_h2[KN * 32];
__device__ __align__(16) float g_t[KN * 32];   // per-node x@b2 term
__device__ __align__(16) int   g_deg[KN];
// prepped w2: [n][PK] bf16, hi image then lo image
__device__ __align__(16) uint8_t g_w2t_c1[512 * PK * 2 * 2];
__device__ __align__(16) uint8_t g_w2t_c2[1024 * PK * 2 * 2];
__device__ __align__(16) uint8_t g_w2t_mu[512 * PK * 2 * 2];
__device__ __align__(16) uint8_t g_w2t_lv[512 * PK * 2 * 2];

// ---------------- helpers ----------------
__device__ __forceinline__ void cp_async16(uint32_t saddr, const void* gptr) {
    asm volatile("cp.async.cg.shared.global [%0], [%1], 16;" ::"r"(saddr), "l"(gptr));
}
__device__ __forceinline__ void cp_commit() { asm volatile("cp.async.commit_group;"); }
__device__ __forceinline__ void cp_wait1() { asm volatile("cp.async.wait_group 1;"); }
__device__ __forceinline__ void cp_wait0() { asm volatile("cp.async.wait_group 0;"); }

__device__ __forceinline__ void mma16816(float* d, const uint32_t* a,
                                         const uint32_t* b) {
    asm volatile(
        "mma.sync.aligned.m16n8k16.row.col.f32.bf16.bf16.f32 "
        "{%0,%1,%2,%3}, {%4,%5,%6,%7}, {%8,%9}, {%0,%1,%2,%3};"
        : "+f"(d[0]), "+f"(d[1]), "+f"(d[2]), "+f"(d[3])
        : "r"(a[0]), "r"(a[1]), "r"(a[2]), "r"(a[3]), "r"(b[0]), "r"(b[1]));
}

// ---------------- zeroing / degree ----------------
__global__ void zero_f_kernel(float* __restrict__ p, int n) {
    int i = blockIdx.x * 256 + threadIdx.x;
    int i4 = i * 4;
    if (i4 + 3 < n) *(float4*)(p + i4) = make_float4(0.f, 0.f, 0.f, 0.f);
    else for (int k = i4; k < n; k++) p[k] = 0.f;
}
__global__ void zero_i_kernel(int* __restrict__ p, int n) {
    int i = blockIdx.x * 256 + threadIdx.x;
    if (i < n) p[i] = 0;
}
__global__ void deg_kernel(const int* __restrict__ dst) {
    int i = blockIdx.x * 256 + threadIdx.x;
    if (i < KE) atomicAdd(&g_deg[dst[i]], 1);
}

// ---------------- w2 prep: transpose + bf16 hi/lo split ----------------
__global__ void prep_w2_kernel(const float* __restrict__ w2, int dd,
                               uint8_t* __restrict__ outb) {
    int idx = blockIdx.x * 256 + threadIdx.x;
    if (idx >= dd * 128) return;
    int n = idx >> 7, k = idx & 127;
    float v = w2[k * dd + n];
    __nv_bfloat16 hi = __float2bfloat16(v);
    __nv_bfloat16 lo = __float2bfloat16(v - __bfloat162float(hi));
    int off = (n * PK + k) * 2;
    int loq = dd * PK * 2;
    *(__nv_bfloat16*)(outb + off) = hi;
    *(__nv_bfloat16*)(outb + loq + off) = lo;
}

// ---------------- per-node x@b2 ----------------
template <int DIN, int DOUT>
__global__ __launch_bounds__(256)
void xb2_kernel(const float* __restrict__ xin, const float* __restrict__ b2,
                float* __restrict__ t) {
    __shared__ float sb[DIN * DOUT];
    int tid = threadIdx.x;
    for (int i = tid; i < DIN * DOUT; i += 256) sb[i] = b2[i];
    __syncthreads();
    int idx = blockIdx.x * 256 + tid;
    if (idx >= KN * DOUT) return;
    int n = idx / DOUT, o = idx % DOUT;
    float s = 0.f;
#pragma unroll
    for (int i = 0; i < DIN; i++) s = fmaf(xin[n * DIN + i], sb[i * DOUT + o], s);
    t[idx] = s;
}

// ---------------- HMMA edge kernel: 4 warps x 32 rows, B reuse 2x ----------
// 128 edges/block, 128 threads (4 warps). Warp w owns rows [32w, 32w+32) as
// two m16 tiles; B fragments loaded once per (k16,n8) feed 6 MMAs (3-split x
// 2 m-tiles) -> B crossbar wavefronts halve vs 8-warp layout. A fragments for
// both m-tiles hoisted to registers (chunk-invariant).
template <int DIN, int DOUT>
__global__ __launch_bounds__(128, 2)
void edge_mma_kernel(const float* __restrict__ xin,
                     const float* __restrict__ ea,
                     const int* __restrict__ src,
                     const int* __restrict__ dst,
                     const float* __restrict__ w1,
                     const float* __restrict__ b1,
                     const uint8_t* __restrict__ w2t,
                     const float* __restrict__ tnode,
                     float* __restrict__ agg) {
    constexpr int DD = DIN * DOUT;
    constexpr int NCH = DD / 32;            // 32-col chunks
    constexpr int NO = DOUT / 4;            // o-slots per thread (8 or 4)
    constexpr int ASZ = 128 * PK * 2;       // per A image
    constexpr int BHALF = 32 * PK * 2;      // 8704 B per split per chunk
    constexpr int BSZ = 2 * BHALF;          // 17408
    const int LOQ = DD * PK * 2;            // lo-image offset in w2t

    extern __shared__ char shb[];
    uint8_t* A_hi = (uint8_t*)shb;
    uint8_t* A_lo = A_hi + ASZ;
    uint8_t* Bbuf0 = A_lo + ASZ;
    uint8_t* Bbuf1 = Bbuf0 + BSZ;
    // prologue overlays inside the two B buffers (8.5KB < 34.8KB)
    float* sea = (float*)Bbuf0;
    float* sw1 = sea + 1024;
    float* sb1 = sw1 + 1024;

    const int tid = threadIdx.x;
    const int lane = tid & 31, warp = tid >> 5;
    const int e0 = blockIdx.x * 128;

    // ---- prologue staging (128 threads) ----
    for (int i = tid; i < 1024; i += 128) sw1[i] = w1[i];
    if (tid < 128) sb1[tid] = b1[tid];
    for (int i = tid; i < 1024; i += 128) {
        long long g = (long long)e0 * 8 + i;
        sea[i] = (g < (long long)KE * 8) ? ea[g] : 0.f;
    }
    __syncthreads();

    // ---- edge MLP -> split bf16 A images ----
    for (int idx = tid; idx < 16384; idx += 128) {
        int e = idx >> 7, k = idx & 127;
        float s = sb1[k];
#pragma unroll
        for (int j = 0; j < 8; j++) s = fmaf(sea[e * 8 + j], sw1[j * 128 + k], s);
        s = fmaxf(s, 0.f);
        __nv_bfloat16 hi = __float2bfloat16(s);
        __nv_bfloat16 lo = __float2bfloat16(s - __bfloat162float(hi));
        int off = (e * PK + k) * 2;
        *(__nv_bfloat16*)(A_hi + off) = hi;
        *(__nv_bfloat16*)(A_lo + off) = lo;
    }
    __syncthreads();   // overlays dead; A ready; B buffers free

    // ---- per-thread edge registers (4 edges: 2 m-tiles x 2 row-groups) ----
    const int gr = lane >> 2;          // 0..7
    const int c2 = (lane & 3) * 2;     // 0,2,4,6
    int ge[4];
    bool ga[4];
    int sv[4], dv[4];
#pragma unroll
    for (int m = 0; m < 2; m++)
#pragma unroll
        for (int p = 0; p < 2; p++) {
            int idx = m * 2 + p;
            ge[idx] = e0 + warp * 32 + m * 16 + gr + p * 8;
            ga[idx] = ge[idx] < KE;
            sv[idx] = ga[idx] ? src[ge[idx]] : 0;
            dv[idx] = ga[idx] ? dst[ge[idx]] : 0;
        }

    // ---- hoist chunk-invariant A fragments (both m-tiles) into registers ----
    uint32_t ahr[2][8][4], alr[2][8][4];
#pragma unroll
    for (int m = 0; m < 2; m++) {
        const int rA = warp * 32 + m * 16 + gr;
#pragma unroll
        for (int k16 = 0; k16 < 8; k16++) {
            const int kb = k16 * 16;
            ahr[m][k16][0] = *(const uint32_t*)(A_hi + (rA * PK + kb + c2) * 2);
            ahr[m][k16][1] = *(const uint32_t*)(A_hi + ((rA + 8) * PK + kb + c2) * 2);
            ahr[m][k16][2] = *(const uint32_t*)(A_hi + (rA * PK + kb + c2 + 8) * 2);
            ahr[m][k16][3] = *(const uint32_t*)(A_hi + ((rA + 8) * PK + kb + c2 + 8) * 2);
            alr[m][k16][0] = *(const uint32_t*)(A_lo + (rA * PK + kb + c2) * 2);
            alr[m][k16][1] = *(const uint32_t*)(A_lo + ((rA + 8) * PK + kb + c2) * 2);
            alr[m][k16][2] = *(const uint32_t*)(A_lo + (rA * PK + kb + c2 + 8) * 2);
            alr[m][k16][3] = *(const uint32_t*)(A_lo + ((rA + 8) * PK + kb + c2 + 8) * 2);
        }
    }

    // ---- prefetch B chunks 0 and 1 ----
    {
        uint32_t s0 = (uint32_t)__cvta_generic_to_shared(Bbuf0);
        uint32_t s1 = (uint32_t)__cvta_generic_to_shared(Bbuf1);
        for (int j = tid; j < BHALF / 16; j += 128) {
            cp_async16(s0 + j * 16, w2t + j * 16);
            cp_async16(s0 + BHALF + j * 16, w2t + LOQ + j * 16);
        }
        cp_commit();
        for (int j = tid; j < BHALF / 16; j += 128) {
            cp_async16(s1 + j * 16, w2t + BHALF + j * 16);
            cp_async16(s1 + BHALF + j * 16, w2t + LOQ + BHALF + j * 16);
        }
        cp_commit();
    }

    float msg[4][NO];
#pragma unroll
    for (int p = 0; p < 4; p++)
#pragma unroll
        for (int s = 0; s < NO; s++) msg[p][s] = 0.f;

    for (int nc = 0; nc < NCH; nc++) {
        if (nc + 1 < NCH) cp_wait1(); else cp_wait0();
        __syncthreads();   // chunk nc resident; prior buffer fully consumed

        const uint8_t* Bc = (nc & 1) ? Bbuf1 : Bbuf0;
        const uint8_t* Bh = Bc;
        const uint8_t* Bl = Bc + BHALF;

        float d[2][4][4];
#pragma unroll
        for (int m = 0; m < 2; m++)
#pragma unroll
            for (int n8 = 0; n8 < 4; n8++)
#pragma unroll
                for (int q = 0; q < 4; q++) d[m][n8][q] = 0.f;

#pragma unroll
        for (int k16 = 0; k16 < 8; k16++) {
            const int kb = k16 * 16;
#pragma unroll
            for (int n8 = 0; n8 < 4; n8++) {
                const int gn = n8 * 8 + gr;
                uint32_t bh[2], bl[2];
                bh[0] = *(const uint32_t*)(Bh + (gn * PK + kb + c2) * 2);
                bh[1] = *(const uint32_t*)(Bh + (gn * PK + kb + c2 + 8) * 2);
                bl[0] = *(const uint32_t*)(Bl + (gn * PK + kb + c2) * 2);
                bl[1] = *(const uint32_t*)(Bl + (gn * PK + kb + c2 + 8) * 2);
#pragma unroll
                for (int m = 0; m < 2; m++) {
                    mma16816(d[m][n8], ahr[m][k16], bh);
                    mma16816(d[m][n8], ahr[m][k16], bl);
                    mma16816(d[m][n8], alr[m][k16], bh);
                }
            }
        }

        // ---- fold with x (LDG, L1-hot) ----
        if (DOUT == 32) {
#pragma unroll
            for (int m = 0; m < 2; m++)
#pragma unroll
                for (int p = 0; p < 2; p++) {
                    int idx = m * 2 + p;
                    float xv = ga[idx] ? xin[(long long)sv[idx] * DIN + nc] : 0.f;
#pragma unroll
                    for (int n8 = 0; n8 < 4; n8++) {
                        msg[idx][n8 * 2]     += xv * d[m][n8][p * 2];
                        msg[idx][n8 * 2 + 1] += xv * d[m][n8][p * 2 + 1];
                    }
                }
        } else {  // DOUT == 16
#pragma unroll
            for (int m = 0; m < 2; m++)
#pragma unroll
                for (int p = 0; p < 2; p++) {
                    int idx = m * 2 + p;
                    const float* xp = xin + (long long)sv[idx] * DIN;
                    float x0 = ga[idx] ? xp[nc * 2] : 0.f;
                    float x1 = ga[idx] ? xp[nc * 2 + 1] : 0.f;
#pragma unroll
                    for (int n8 = 0; n8 < 4; n8++) {
                        float xv = (n8 < 2) ? x0 : x1;
                        int slot = (n8 & 1) * 2;
                        msg[idx][slot]     += xv * d[m][n8][p * 2];
                        msg[idx][slot + 1] += xv * d[m][n8][p * 2 + 1];
                    }
                }
        }
        __syncthreads();   // all warps done with this buffer

        if (nc + 2 < NCH) {
            uint8_t* nb = (nc & 1) ? Bbuf1 : Bbuf0;
            uint32_t sb = (uint32_t)__cvta_generic_to_shared(nb);
            const uint8_t* gh = w2t + (long long)(nc + 2) * BHALF;
            const uint8_t* gl = w2t + LOQ + (long long)(nc + 2) * BHALF;
            for (int j = tid; j < BHALF / 16; j += 128) {
                cp_async16(sb + j * 16, gh + j * 16);
                cp_async16(sb + BHALF + j * 16, gl + j * 16);
            }
        }
        cp_commit();       // uniform group accounting
    }

    // ---- scatter: single owner per (e,o); add per-node x@b2 term ----
#pragma unroll
    for (int idx = 0; idx < 4; idx++) {
        if (ga[idx]) {
            const float* tn = tnode + (long long)sv[idx] * DOUT;
            float* ap = agg + (long long)dv[idx] * DOUT;
#pragma unroll
            for (int s = 0; s < NO; s++) {
                int o = (s >> 1) * 8 + c2 + (s & 1);
                atomicAdd(ap + o, msg[idx][s] + tn[o]);
            }
        }
    }
}

// ---------------- node epilogue: mean + root GEMM + bias (+relu) ----------------
template <int DIN, int DOUT, bool MEAN, bool RELU>
__global__ __launch_bounds__(256)
void node_kernel(const float* __restrict__ xin, const float* __restrict__ agg,
                 const float* __restrict__ root, const float* __restrict__ bias,
                 const int* __restrict__ deg, float* __restrict__ out) {
    __shared__ float sroot[DIN * DOUT];
    __shared__ float sbias[DOUT];
    int tid = threadIdx.x;
    for (int i = tid; i < DIN * DOUT; i += 256) sroot[i] = root[i];
    if (tid < DOUT) sbias[tid] = bias[tid];
    __syncthreads();
    int idx = blockIdx.x * 256 + tid;
    if (idx >= KN * DOUT) return;
    int n = idx / DOUT, o = idx % DOUT;
    float v = agg[idx];
    if (MEAN) {
        int d = deg[n];
        v *= 1.f / (d > 0 ? (float)d : 1.f);
    }
    const float* xr = xin + n * DIN;
#pragma unroll
    for (int i = 0; i < DIN; i++) v = fmaf(xr[i], sroot[i * DOUT + o], v);
    v += sbias[o];
    if (RELU) v = fmaxf(v, 0.f);
    out[idx] = v;
}

// ---------------- launch ----------------
static constexpr int smem_mma() {
    return 2 * (128 * PK * 2) + 2 * (2 * 32 * PK * 2);  // 104,448
}

extern "C" void kernel_launch(void* const* d_in, const int* in_sizes, int n_in,
                              void* d_out, int out_size) {
    const float* x = (const float*)d_in[0];
    const int* ei = (const int*)d_in[1];  // int32 (JAX x64-disabled downcast)
    const float* ea = (const float*)d_in[2];
    auto f = [&](int i) { return (const float*)d_in[i]; };
    float* out = (float*)d_out;
    const int* src = ei;
    const int* dstp = ei + KE;

    void *agg_p, *deg_p, *h1_p, *h2_p, *t_p, *wc1, *wc2, *wmu, *wlv;
    cudaGetSymbolAddress(&agg_p, g_agg);
    cudaGetSymbolAddress(&deg_p, g_deg);
    cudaGetSymbolAddress(&h1_p, g_h1);
    cudaGetSymbolAddress(&h2_p, g_h2);
    cudaGetSymbolAddress(&t_p, g_t);
    cudaGetSymbolAddress(&wc1, g_w2t_c1);
    cudaGetSymbolAddress(&wc2, g_w2t_c2);
    cudaGetSymbolAddress(&wmu, g_w2t_mu);
    cudaGetSymbolAddress(&wlv, g_w2t_lv);

    cudaFuncSetAttribute(edge_mma_kernel<16, 32>,
                         cudaFuncAttributeMaxDynamicSharedMemorySize, smem_mma());
    cudaFuncSetAttribute(edge_mma_kernel<32, 32>,
                         cudaFuncAttributeMaxDynamicSharedMemorySize, smem_mma());
    cudaFuncSetAttribute(edge_mma_kernel<32, 16>,
                         cudaFuncAttributeMaxDynamicSharedMemorySize, smem_mma());

    const int TB = (KE + 127) / 128;
    const int ZB32 = (KN * 32 / 4 + 255) / 256;
    const int ZB16 = (KN * 16 / 4 + 255) / 256;
    const int NB32 = (KN * 32 + 255) / 256;
    const int NB16 = (KN * 16 + 255) / 256;

    // prep w2 images (in-graph, deterministic)
    prep_w2_kernel<<<(512 * 128 + 255) / 256, 256>>>(f(5), 512, (uint8_t*)wc1);
    prep_w2_kernel<<<(1024 * 128 + 255) / 256, 256>>>(f(11), 1024, (uint8_t*)wc2);
    prep_w2_kernel<<<(512 * 128 + 255) / 256, 256>>>(f(17), 512, (uint8_t*)wmu);
    prep_w2_kernel<<<(512 * 128 + 255) / 256, 256>>>(f(23), 512, (uint8_t*)wlv);

    zero_i_kernel<<<(KN + 255) / 256, 256>>>((int*)deg_p, KN);
    deg_kernel<<<(KE + 255) / 256, 256>>>(dstp);

    // conv1: 16 -> 32, mean, relu
    zero_f_kernel<<<ZB32, 256>>>((float*)agg_p, KN * 32);
    xb2_kernel<16, 32><<<NB32, 256>>>(x, f(6), (float*)t_p);
    edge_mma_kernel<16, 32><<<TB, 128, smem_mma()>>>(
        x, ea, src, dstp, f(3), f(4), (const uint8_t*)wc1, (const float*)t_p,
        (float*)agg_p);
    node_kernel<16, 32, true, true><<<NB32, 256>>>(
        x, (const float*)agg_p, f(7), f(8), (const int*)deg_p, (float*)h1_p);

    // conv2: 32 -> 32, mean, relu
    zero_f_kernel<<<ZB32, 256>>>((float*)agg_p, KN * 32);
    xb2_kernel<32, 32><<<NB32, 256>>>((const float*)h1_p, f(12), (float*)t_p);
    edge_mma_kernel<32, 32><<<TB, 128, smem_mma()>>>(
        (const float*)h1_p, ea, src, dstp, f(9), f(10), (const uint8_t*)wc2,
        (const float*)t_p, (float*)agg_p);
    node_kernel<32, 32, true, true><<<NB32, 256>>>(
        (const float*)h1_p, (const float*)agg_p, f(13), f(14), (const int*)deg_p,
        (float*)h2_p);

    // mu: 32 -> 16, sum
    zero_f_kernel<<<ZB16, 256>>>((float*)agg_p, KN * 16);
    xb2_kernel<32, 16><<<NB16, 256>>>((const float*)h2_p, f(18), (float*)t_p);
    edge_mma_kernel<32, 16><<<TB, 128, smem_mma()>>>(
        (const float*)h2_p, ea, src, dstp, f(15), f(16), (const uint8_t*)wmu,
        (const float*)t_p, (float*)agg_p);
    node_kernel<32, 16, false, false><<<NB16, 256>>>(
        (const float*)h2_p, (const float*)agg_p, f(19), f(20), (const int*)deg_p,
        out);

    // logvar: 32 -> 16, sum
    zero_f_kernel<<<ZB16, 256>>>((float*)agg_p, KN * 16);
    xb2_kernel<32, 16><<<NB16, 256>>>((const float*)h2_p, f(24), (float*)t_p);
    edge_mma_kernel<32, 16><<<TB, 128, smem_mma()>>>(
        (const float*)h2_p, ea, src, dstp, f(21), f(22), (const uint8_t*)wlv,
        (const float*)t_p, (float*)agg_p);
    node_kernel<32, 16, false, false><<<NB16, 256>>>(
        (const float*)h2_p, (const float*)agg_p, f(25), f(26), (const int*)deg_p,
        out + KN * 16);
}

// round 14
// speedup vs baseline: 1.0529x; 1.0529x over previous
#include <cuda_runtime.h>
#include <cuda_bf16.h>
#include <cstdint>

// Problem constants
static constexpr int KN = 50000;   // nodes
static constexpr int KE = 150000;  // edges
// dims: IN=16, HID=32, LAT=16, EF=8, HE=128
static constexpr int PK = 136;     // bf16 pitch for [n][k] / [e][k] tiles

// ---------------- device scratch (static, no allocation) ----------------
__device__ __align__(16) float g_agg[KN * 32];
__device__ __align__(16) float g_h1[KN * 32];
__device__ __align__(16) float g_h2[KN * 32];
__device__ __align__(16) float g_t[KN * 32];   // per-node x@b2 term
__device__ __align__(16) int   g_deg[KN];
// prepped w2: [n][PK] bf16, hi image then lo image
__device__ __align__(16) uint8_t g_w2t_c1[512 * PK * 2 * 2];
__device__ __align__(16) uint8_t g_w2t_c2[1024 * PK * 2 * 2];
__device__ __align__(16) uint8_t g_w2t_mu[512 * PK * 2 * 2];
__device__ __align__(16) uint8_t g_w2t_lv[512 * PK * 2 * 2];

// ---------------- helpers ----------------
__device__ __forceinline__ void cp_async16(uint32_t saddr, const void* gptr) {
    asm volatile("cp.async.cg.shared.global [%0], [%1], 16;" ::"r"(saddr), "l"(gptr));
}
__device__ __forceinline__ void cp_commit() { asm volatile("cp.async.commit_group;"); }
__device__ __forceinline__ void cp_wait1() { asm volatile("cp.async.wait_group 1;"); }
__device__ __forceinline__ void cp_wait0() { asm volatile("cp.async.wait_group 0;"); }

__device__ __forceinline__ void mma16816(float* d, const uint32_t* a,
                                         const uint32_t* b) {
    asm volatile(
        "mma.sync.aligned.m16n8k16.row.col.f32.bf16.bf16.f32 "
        "{%0,%1,%2,%3}, {%4,%5,%6,%7}, {%8,%9}, {%0,%1,%2,%3};"
        : "+f"(d[0]), "+f"(d[1]), "+f"(d[2]), "+f"(d[3])
        : "r"(a[0]), "r"(a[1]), "r"(a[2]), "r"(a[3]), "r"(b[0]), "r"(b[1]));
}
__device__ __forceinline__ void ldmx4(uint32_t* r, uint32_t addr) {
    asm volatile(
        "ldmatrix.sync.aligned.m8n8.x4.shared.b16 {%0,%1,%2,%3}, [%4];"
        : "=r"(r[0]), "=r"(r[1]), "=r"(r[2]), "=r"(r[3]) : "r"(addr));
}

// ---------------- zeroing / degree ----------------
__global__ void zero_f_kernel(float* __restrict__ p, int n) {
    int i = blockIdx.x * 256 + threadIdx.x;
    int i4 = i * 4;
    if (i4 + 3 < n) *(float4*)(p + i4) = make_float4(0.f, 0.f, 0.f, 0.f);
    else for (int k = i4; k < n; k++) p[k] = 0.f;
}
__global__ void zero_i_kernel(int* __restrict__ p, int n) {
    int i = blockIdx.x * 256 + threadIdx.x;
    if (i < n) p[i] = 0;
}
__global__ void deg_kernel(const int* __restrict__ dst) {
    int i = blockIdx.x * 256 + threadIdx.x;
    if (i < KE) atomicAdd(&g_deg[dst[i]], 1);
}

// ---------------- w2 prep: transpose + bf16 hi/lo split ----------------
__global__ void prep_w2_kernel(const float* __restrict__ w2, int dd,
                               uint8_t* __restrict__ outb) {
    int idx = blockIdx.x * 256 + threadIdx.x;
    if (idx >= dd * 128) return;
    int n = idx >> 7, k = idx & 127;
    float v = w2[k * dd + n];
    __nv_bfloat16 hi = __float2bfloat16(v);
    __nv_bfloat16 lo = __float2bfloat16(v - __bfloat162float(hi));
    int off = (n * PK + k) * 2;
    int loq = dd * PK * 2;
    *(__nv_bfloat16*)(outb + off) = hi;
    *(__nv_bfloat16*)(outb + loq + off) = lo;
}

// ---------------- per-node x@b2 ----------------
template <int DIN, int DOUT>
__global__ __launch_bounds__(256)
void xb2_kernel(const float* __restrict__ xin, const float* __restrict__ b2,
                float* __restrict__ t) {
    __shared__ float sb[DIN * DOUT];
    int tid = threadIdx.x;
    for (int i = tid; i < DIN * DOUT; i += 256) sb[i] = b2[i];
    __syncthreads();
    int idx = blockIdx.x * 256 + tid;
    if (idx >= KN * DOUT) return;
    int n = idx / DOUT, o = idx % DOUT;
    float s = 0.f;
#pragma unroll
    for (int i = 0; i < DIN; i++) s = fmaf(xin[n * DIN + i], sb[i * DOUT + o], s);
    t[idx] = s;
}

// ---------------- HMMA edge kernel: R11 layout + LDSM B loads ----------
// 128 edges/block, 8 warps x 16 rows. A fragments chunk-invariant in regs.
// B fragments via ldmatrix.x4 (1 instr per 2 n8-groups) -> chunk-loop issue
// slots drop ~43% vs scalar LDS.32 loads. hi processed then regs reloaded
// with lo (peak 8 temp regs) to stay under the occ-2 register cap.
template <int DIN, int DOUT>
__global__ __launch_bounds__(256, 2)
void edge_mma_kernel(const float* __restrict__ xin,
                     const float* __restrict__ ea,
                     const int* __restrict__ src,
                     const int* __restrict__ dst,
                     const float* __restrict__ w1,
                     const float* __restrict__ b1,
                     const uint8_t* __restrict__ w2t,
                     const float* __restrict__ tnode,
                     float* __restrict__ agg) {
    constexpr int DD = DIN * DOUT;
    constexpr int NCH = DD / 32;            // 32-col chunks
    constexpr int NO = DOUT / 4;            // o-slots per thread (8 or 4)
    constexpr int ASZ = 128 * PK * 2;       // per A image
    constexpr int BHALF = 32 * PK * 2;      // 8704 B per split per chunk
    constexpr int BSZ = 2 * BHALF;          // 17408
    const int LOQ = DD * PK * 2;            // lo-image offset in w2t

    extern __shared__ char shb[];
    uint8_t* A_hi = (uint8_t*)shb;
    uint8_t* A_lo = A_hi + ASZ;
    uint8_t* Bbuf0 = A_lo + ASZ;
    uint8_t* Bbuf1 = Bbuf0 + BSZ;
    // prologue overlays inside the two B buffers (8.5KB < 34.8KB)
    float* sea = (float*)Bbuf0;
    float* sw1 = sea + 1024;
    float* sb1 = sw1 + 1024;

    const int tid = threadIdx.x;
    const int lane = tid & 31, warp = tid >> 5;
    const int e0 = blockIdx.x * 128;

    // ---- prologue staging ----
    for (int i = tid; i < 1024; i += 256) sw1[i] = w1[i];
    if (tid < 128) sb1[tid] = b1[tid];
    for (int i = tid; i < 1024; i += 256) {
        long long g = (long long)e0 * 8 + i;
        sea[i] = (g < (long long)KE * 8) ? ea[g] : 0.f;
    }
    __syncthreads();

    // ---- edge MLP -> split bf16 A images ----
    for (int idx = tid; idx < 16384; idx += 256) {
        int e = idx >> 7, k = idx & 127;
        float s = sb1[k];
#pragma unroll
        for (int j = 0; j < 8; j++) s = fmaf(sea[e * 8 + j], sw1[j * 128 + k], s);
        s = fmaxf(s, 0.f);
        __nv_bfloat16 hi = __float2bfloat16(s);
        __nv_bfloat16 lo = __float2bfloat16(s - __bfloat162float(hi));
        int off = (e * PK + k) * 2;
        *(__nv_bfloat16*)(A_hi + off) = hi;
        *(__nv_bfloat16*)(A_lo + off) = lo;
    }
    __syncthreads();   // overlays dead; A ready; B buffers free

    // ---- per-thread edge registers ----
    const int gr = lane >> 2;          // 0..7
    const int c2 = (lane & 3) * 2;     // 0,2,4,6
    const int rA = warp * 16 + gr;
    const int ge0 = e0 + rA, ge1 = e0 + rA + 8;
    const bool a0 = ge0 < KE, a1 = ge1 < KE;
    const int sv0 = a0 ? src[ge0] : 0;
    const int sv1 = a1 ? src[ge1] : 0;
    const int dv0 = a0 ? dst[ge0] : 0;
    const int dv1 = a1 ? dst[ge1] : 0;
    const float* x0p = xin + (long long)sv0 * DIN;
    const float* x1p = xin + (long long)sv1 * DIN;

    // ldmatrix lane address offsets: group g=lane/8 -> (n8pair half, k half)
    const int gg = lane >> 3, rr = lane & 7;
    const uint32_t bOffNp0 = (uint32_t)((((gg >> 1) * 8 + rr) * PK + (gg & 1) * 8) * 2);
    const uint32_t bOffNp1 = bOffNp0 + (uint32_t)(16 * PK * 2);

    // ---- hoist chunk-invariant A fragments into registers ----
    uint32_t ahr[8][4], alr[8][4];
#pragma unroll
    for (int k16 = 0; k16 < 8; k16++) {
        const int kb = k16 * 16;
        ahr[k16][0] = *(const uint32_t*)(A_hi + (rA * PK + kb + c2) * 2);
        ahr[k16][1] = *(const uint32_t*)(A_hi + ((rA + 8) * PK + kb + c2) * 2);
        ahr[k16][2] = *(const uint32_t*)(A_hi + (rA * PK + kb + c2 + 8) * 2);
        ahr[k16][3] = *(const uint32_t*)(A_hi + ((rA + 8) * PK + kb + c2 + 8) * 2);
        alr[k16][0] = *(const uint32_t*)(A_lo + (rA * PK + kb + c2) * 2);
        alr[k16][1] = *(const uint32_t*)(A_lo + ((rA + 8) * PK + kb + c2) * 2);
        alr[k16][2] = *(const uint32_t*)(A_lo + (rA * PK + kb + c2 + 8) * 2);
        alr[k16][3] = *(const uint32_t*)(A_lo + ((rA + 8) * PK + kb + c2 + 8) * 2);
    }

    // ---- prefetch B chunks 0 and 1 ----
    {
        uint32_t s0 = (uint32_t)__cvta_generic_to_shared(Bbuf0);
        uint32_t s1 = (uint32_t)__cvta_generic_to_shared(Bbuf1);
        for (int j = tid; j < BHALF / 16; j += 256) {
            cp_async16(s0 + j * 16, w2t + j * 16);
            cp_async16(s0 + BHALF + j * 16, w2t + LOQ + j * 16);
        }
        cp_commit();
        for (int j = tid; j < BHALF / 16; j += 256) {
            cp_async16(s1 + j * 16, w2t + BHALF + j * 16);
            cp_async16(s1 + BHALF + j * 16, w2t + LOQ + BHALF + j * 16);
        }
        cp_commit();
    }

    const uint32_t bu0 = (uint32_t)__cvta_generic_to_shared(Bbuf0);
    const uint32_t bu1 = (uint32_t)__cvta_generic_to_shared(Bbuf1);

    float msg[2][NO];
#pragma unroll
    for (int p = 0; p < 2; p++)
#pragma unroll
        for (int s = 0; s < NO; s++) msg[p][s] = 0.f;

    for (int nc = 0; nc < NCH; nc++) {
        if (nc + 1 < NCH) cp_wait1(); else cp_wait0();
        __syncthreads();   // chunk nc resident; prior buffer fully consumed

        const uint32_t bu = (nc & 1) ? bu1 : bu0;

        float d[4][4];
#pragma unroll
        for (int n8 = 0; n8 < 4; n8++)
#pragma unroll
            for (int q = 0; q < 4; q++) d[n8][q] = 0.f;

#pragma unroll
        for (int k16 = 0; k16 < 8; k16++) {
            const uint32_t kb2 = k16 * 32;   // 16 k-values * 2 bytes
            uint32_t b0[4], b1[4];
            // hi split: n8 groups 0,1 then 2,3
            ldmx4(b0, bu + bOffNp0 + kb2);
            ldmx4(b1, bu + bOffNp1 + kb2);
            mma16816(d[0], ahr[k16], b0);
            mma16816(d[0], alr[k16], b0);
            mma16816(d[1], ahr[k16], b0 + 2);
            mma16816(d[1], alr[k16], b0 + 2);
            mma16816(d[2], ahr[k16], b1);
            mma16816(d[2], alr[k16], b1);
            mma16816(d[3], ahr[k16], b1 + 2);
            mma16816(d[3], alr[k16], b1 + 2);
            // lo split (reuse regs): only ah x bl needed
            ldmx4(b0, bu + BHALF + bOffNp0 + kb2);
            ldmx4(b1, bu + BHALF + bOffNp1 + kb2);
            mma16816(d[0], ahr[k16], b0);
            mma16816(d[1], ahr[k16], b0 + 2);
            mma16816(d[2], ahr[k16], b1);
            mma16816(d[3], ahr[k16], b1 + 2);
        }

        // ---- fold with x (LDG, L1-hot; 1-2 i values per chunk) ----
        if (DOUT == 32) {
            float xa = x0p[nc];
            float xb = x1p[nc];
#pragma unroll
            for (int n8 = 0; n8 < 4; n8++) {
                msg[0][n8 * 2]     += xa * d[n8][0];
                msg[0][n8 * 2 + 1] += xa * d[n8][1];
                msg[1][n8 * 2]     += xb * d[n8][2];
                msg[1][n8 * 2 + 1] += xb * d[n8][3];
            }
        } else {  // DOUT == 16
            float xa0 = x0p[nc * 2], xa1 = x0p[nc * 2 + 1];
            float xb0 = x1p[nc * 2], xb1 = x1p[nc * 2 + 1];
#pragma unroll
            for (int n8 = 0; n8 < 4; n8++) {
                float xa = (n8 < 2) ? xa0 : xa1;
                float xb = (n8 < 2) ? xb0 : xb1;
                int slot = (n8 & 1) * 2;
                msg[0][slot]     += xa * d[n8][0];
                msg[0][slot + 1] += xa * d[n8][1];
                msg[1][slot]     += xb * d[n8][2];
                msg[1][slot + 1] += xb * d[n8][3];
            }
        }
        __syncthreads();   // all warps done with this buffer

        if (nc + 2 < NCH) {
            uint8_t* nb = (nc & 1) ? Bbuf1 : Bbuf0;
            uint32_t sb = (uint32_t)__cvta_generic_to_shared(nb);
            const uint8_t* gh = w2t + (long long)(nc + 2) * BHALF;
            const uint8_t* gl = w2t + LOQ + (long long)(nc + 2) * BHALF;
            for (int j = tid; j < BHALF / 16; j += 256) {
                cp_async16(sb + j * 16, gh + j * 16);
                cp_async16(sb + BHALF + j * 16, gl + j * 16);
            }
        }
        cp_commit();       // uniform group accounting
    }

    // ---- scatter: single owner per (e,o); add per-node x@b2 term ----
    if (a0) {
        const float* tn = tnode + (long long)sv0 * DOUT;
        float* ap = agg + (long long)dv0 * DOUT;
#pragma unroll
        for (int s = 0; s < NO; s++) {
            int o = (s >> 1) * 8 + c2 + (s & 1);
            atomicAdd(ap + o, msg[0][s] + tn[o]);
        }
    }
    if (a1) {
        const float* tn = tnode + (long long)sv1 * DOUT;
        float* ap = agg + (long long)dv1 * DOUT;
#pragma unroll
        for (int s = 0; s < NO; s++) {
            int o = (s >> 1) * 8 + c2 + (s & 1);
            atomicAdd(ap + o, msg[1][s] + tn[o]);
        }
    }
}

// ---------------- node epilogue: mean + root GEMM + bias (+relu) ----------------
template <int DIN, int DOUT, bool MEAN, bool RELU>
__global__ __launch_bounds__(256)
void node_kernel(const float* __restrict__ xin, const float* __restrict__ agg,
                 const float* __restrict__ root, const float* __restrict__ bias,
                 const int* __restrict__ deg, float* __restrict__ out) {
    __shared__ float sroot[DIN * DOUT];
    __shared__ float sbias[DOUT];
    int tid = threadIdx.x;
    for (int i = tid; i < DIN * DOUT; i += 256) sroot[i] = root[i];
    if (tid < DOUT) sbias[tid] = bias[tid];
    __syncthreads();
    int idx = blockIdx.x * 256 + tid;
    if (idx >= KN * DOUT) return;
    int n = idx / DOUT, o = idx % DOUT;
    float v = agg[idx];
    if (MEAN) {
        int d = deg[n];
        v *= 1.f / (d > 0 ? (float)d : 1.f);
    }
    const float* xr = xin + n * DIN;
#pragma unroll
    for (int i = 0; i < DIN; i++) v = fmaf(xr[i], sroot[i * DOUT + o], v);
    v += sbias[o];
    if (RELU) v = fmaxf(v, 0.f);
    out[idx] = v;
}

// ---------------- launch ----------------
static constexpr int smem_mma() {
    return 2 * (128 * PK * 2) + 2 * (2 * 32 * PK * 2);  // 104,448
}

extern "C" void kernel_launch(void* const* d_in, const int* in_sizes, int n_in,
                              void* d_out, int out_size) {
    const float* x = (const float*)d_in[0];
    const int* ei = (const int*)d_in[1];  // int32 (JAX x64-disabled downcast)
    const float* ea = (const float*)d_in[2];
    auto f = [&](int i) { return (const float*)d_in[i]; };
    float* out = (float*)d_out;
    const int* src = ei;
    const int* dstp = ei + KE;

    void *agg_p, *deg_p, *h1_p, *h2_p, *t_p, *wc1, *wc2, *wmu, *wlv;
    cudaGetSymbolAddress(&agg_p, g_agg);
    cudaGetSymbolAddress(&deg_p, g_deg);
    cudaGetSymbolAddress(&h1_p, g_h1);
    cudaGetSymbolAddress(&h2_p, g_h2);
    cudaGetSymbolAddress(&t_p, g_t);
    cudaGetSymbolAddress(&wc1, g_w2t_c1);
    cudaGetSymbolAddress(&wc2, g_w2t_c2);
    cudaGetSymbolAddress(&wmu, g_w2t_mu);
    cudaGetSymbolAddress(&wlv, g_w2t_lv);

    cudaFuncSetAttribute(edge_mma_kernel<16, 32>,
                         cudaFuncAttributeMaxDynamicSharedMemorySize, smem_mma());
    cudaFuncSetAttribute(edge_mma_kernel<32, 32>,
                         cudaFuncAttributeMaxDynamicSharedMemorySize, smem_mma());
    cudaFuncSetAttribute(edge_mma_kernel<32, 16>,
                         cudaFuncAttributeMaxDynamicSharedMemorySize, smem_mma());

    const int TB = (KE + 127) / 128;
    const int ZB32 = (KN * 32 / 4 + 255) / 256;
    const int ZB16 = (KN * 16 / 4 + 255) / 256;
    const int NB32 = (KN * 32 + 255) / 256;
    const int NB16 = (KN * 16 + 255) / 256;

    // prep w2 images (in-graph, deterministic)
    prep_w2_kernel<<<(512 * 128 + 255) / 256, 256>>>(f(5), 512, (uint8_t*)wc1);
    prep_w2_kernel<<<(1024 * 128 + 255) / 256, 256>>>(f(11), 1024, (uint8_t*)wc2);
    prep_w2_kernel<<<(512 * 128 + 255) / 256, 256>>>(f(17), 512, (uint8_t*)wmu);
    prep_w2_kernel<<<(512 * 128 + 255) / 256, 256>>>(f(23), 512, (uint8_t*)wlv);

    zero_i_kernel<<<(KN + 255) / 256, 256>>>((int*)deg_p, KN);
    deg_kernel<<<(KE + 255) / 256, 256>>>(dstp);

    // conv1: 16 -> 32, mean, relu
    zero_f_kernel<<<ZB32, 256>>>((float*)agg_p, KN * 32);
    xb2_kernel<16, 32><<<NB32, 256>>>(x, f(6), (float*)t_p);
    edge_mma_kernel<16, 32><<<TB, 256, smem_mma()>>>(
        x, ea, src, dstp, f(3), f(4), (const uint8_t*)wc1, (const float*)t_p,
        (float*)agg_p);
    node_kernel<16, 32, true, true><<<NB32, 256>>>(
        x, (const float*)agg_p, f(7), f(8), (const int*)deg_p, (float*)h1_p);

    // conv2: 32 -> 32, mean, relu
    zero_f_kernel<<<ZB32, 256>>>((float*)agg_p, KN * 32);
    xb2_kernel<32, 32><<<NB32, 256>>>((const float*)h1_p, f(12), (float*)t_p);
    edge_mma_kernel<32, 32><<<TB, 256, smem_mma()>>>(
        (const float*)h1_p, ea, src, dstp, f(9), f(10), (const uint8_t*)wc2,
        (const float*)t_p, (float*)agg_p);
    node_kernel<32, 32, true, true><<<NB32, 256>>>(
        (const float*)h1_p, (const float*)agg_p, f(13), f(14), (const int*)deg_p,
        (float*)h2_p);

    // mu: 32 -> 16, sum
    zero_f_kernel<<<ZB16, 256>>>((float*)agg_p, KN * 16);
    xb2_kernel<32, 16><<<NB16, 256>>>((const float*)h2_p, f(18), (float*)t_p);
    edge_mma_kernel<32, 16><<<TB, 256, smem_mma()>>>(
        (const float*)h2_p, ea, src, dstp, f(15), f(16), (const uint8_t*)wmu,
        (const float*)t_p, (float*)agg_p);
    node_kernel<32, 16, false, false><<<NB16, 256>>>(
        (const float*)h2_p, (const float*)agg_p, f(19), f(20), (const int*)deg_p,
        out);

    // logvar: 32 -> 16, sum
    zero_f_kernel<<<ZB16, 256>>>((float*)agg_p, KN * 16);
    xb2_kernel<32, 16><<<NB16, 256>>>((const float*)h2_p, f(24), (float*)t_p);
    edge_mma_kernel<32, 16><<<TB, 256, smem_mma()>>>(
        (const float*)h2_p, ea, src, dstp, f(21), f(22), (const uint8_t*)wlv,
        (const float*)t_p, (float*)agg_p);
    node_kernel<32, 16, false, false><<<NB16, 256>>>(
        (const float*)h2_p, (const float*)agg_p, f(25), f(26), (const int*)deg_p,
        out + KN * 16);
}

// round 15
// speedup vs baseline: 1.0658x; 1.0123x over previous
#include <cuda_runtime.h>
#include <cuda_bf16.h>
#include <cstdint>

// Problem constants
static constexpr int KN = 50000;   // nodes
static constexpr int KE = 150000;  // edges
// dims: IN=16, HID=32, LAT=16, EF=8, HE=128
static constexpr int PK = 136;     // bf16 pitch for [n][k] / [e][k] tiles

// ---------------- device scratch (static, no allocation) ----------------
__device__ __align__(16) float g_agg[KN * 32];
__device__ __align__(16) float g_h1[KN * 32];
__device__ __align__(16) float g_h2[KN * 32];
__device__ __align__(16) float g_t[KN * 32];   // per-node x@b2 term
__device__ __align__(16) int   g_deg[KN];
// prepped w2: [n][PK] bf16, hi image then lo image
__device__ __align__(16) uint8_t g_w2t_c1[512 * PK * 2 * 2];
__device__ __align__(16) uint8_t g_w2t_c2[1024 * PK * 2 * 2];
__device__ __align__(16) uint8_t g_w2t_mu[512 * PK * 2 * 2];
__device__ __align__(16) uint8_t g_w2t_lv[512 * PK * 2 * 2];

// ---------------- helpers ----------------
__device__ __forceinline__ void cp_async16(uint32_t saddr, const void* gptr) {
    asm volatile("cp.async.cg.shared.global [%0], [%1], 16;" ::"r"(saddr), "l"(gptr));
}
__device__ __forceinline__ void cp_commit() { asm volatile("cp.async.commit_group;"); }
__device__ __forceinline__ void cp_wait1() { asm volatile("cp.async.wait_group 1;"); }

__device__ __forceinline__ void mma16816(float* d, const uint32_t* a,
                                         const uint32_t* b) {
    asm volatile(
        "mma.sync.aligned.m16n8k16.row.col.f32.bf16.bf16.f32 "
        "{%0,%1,%2,%3}, {%4,%5,%6,%7}, {%8,%9}, {%0,%1,%2,%3};"
        : "+f"(d[0]), "+f"(d[1]), "+f"(d[2]), "+f"(d[3])
        : "r"(a[0]), "r"(a[1]), "r"(a[2]), "r"(a[3]), "r"(b[0]), "r"(b[1]));
}
__device__ __forceinline__ void ldmx4(uint32_t* r, uint32_t addr) {
    asm volatile(
        "ldmatrix.sync.aligned.m8n8.x4.shared.b16 {%0,%1,%2,%3}, [%4];"
        : "=r"(r[0]), "=r"(r[1]), "=r"(r[2]), "=r"(r[3]) : "r"(addr));
}
// f32x2 packed helpers (Blackwell FFMA2)
__device__ __forceinline__ unsigned long long pack2(float x, float y) {
    unsigned long long r;
    asm("mov.b64 %0, {%1, %2};" : "=l"(r) : "f"(x), "f"(y));
    return r;
}
__device__ __forceinline__ void unpack2(unsigned long long v, float& lo, float& hi) {
    asm("mov.b64 {%0, %1}, %2;" : "=f"(lo), "=f"(hi) : "l"(v));
}
__device__ __forceinline__ unsigned long long ffma2(unsigned long long a,
                                                    unsigned long long b,
                                                    unsigned long long c) {
    unsigned long long d;
    asm("fma.rn.f32x2 %0, %1, %2, %3;" : "=l"(d) : "l"(a), "l"(b), "l"(c));
    return d;
}

// ---------------- zeroing / degree ----------------
__global__ void zero_f_kernel(float* __restrict__ p, int n) {
    int i = blockIdx.x * 256 + threadIdx.x;
    int i4 = i * 4;
    if (i4 + 3 < n) *(float4*)(p + i4) = make_float4(0.f, 0.f, 0.f, 0.f);
    else for (int k = i4; k < n; k++) p[k] = 0.f;
}
__global__ void zero_i_kernel(int* __restrict__ p, int n) {
    int i = blockIdx.x * 256 + threadIdx.x;
    if (i < n) p[i] = 0;
}
__global__ void deg_kernel(const int* __restrict__ dst) {
    int i = blockIdx.x * 256 + threadIdx.x;
    if (i < KE) atomicAdd(&g_deg[dst[i]], 1);
}

// ---------------- w2 prep: transpose + bf16 hi/lo split ----------------
__global__ void prep_w2_kernel(const float* __restrict__ w2, int dd,
                               uint8_t* __restrict__ outb) {
    int idx = blockIdx.x * 256 + threadIdx.x;
    if (idx >= dd * 128) return;
    int n = idx >> 7, k = idx & 127;
    float v = w2[k * dd + n];
    __nv_bfloat16 hi = __float2bfloat16(v);
    __nv_bfloat16 lo = __float2bfloat16(v - __bfloat162float(hi));
    int off = (n * PK + k) * 2;
    int loq = dd * PK * 2;
    *(__nv_bfloat16*)(outb + off) = hi;
    *(__nv_bfloat16*)(outb + loq + off) = lo;
}

// ---------------- per-node x@b2 ----------------
template <int DIN, int DOUT>
__global__ __launch_bounds__(256)
void xb2_kernel(const float* __restrict__ xin, const float* __restrict__ b2,
                float* __restrict__ t) {
    __shared__ float sb[DIN * DOUT];
    int tid = threadIdx.x;
    for (int i = tid; i < DIN * DOUT; i += 256) sb[i] = b2[i];
    __syncthreads();
    int idx = blockIdx.x * 256 + tid;
    if (idx >= KN * DOUT) return;
    int n = idx / DOUT, o = idx % DOUT;
    float s = 0.f;
#pragma unroll
    for (int i = 0; i < DIN; i++) s = fmaf(xin[n * DIN + i], sb[i * DOUT + o], s);
    t[idx] = s;
}

// ---------------- HMMA edge kernel: LDSM + triple-buffer (1 barrier/chunk) --
// 128 edges/block, 8 warps x 16 rows, occ-2. A fragments hoisted via LDSM;
// both A smem images are dead after the hoist, so B buffer #2 overlays A_lo.
// Per chunk: wait_group(1) -> ONE syncthreads -> prefetch nc+2 -> MMA/fold.
template <int DIN, int DOUT>
__global__ __launch_bounds__(256, 2)
void edge_mma_kernel(const float* __restrict__ xin,
                     const float* __restrict__ ea,
                     const int* __restrict__ src,
                     const int* __restrict__ dst,
                     const float* __restrict__ w1,
                     const float* __restrict__ b1,
                     const uint8_t* __restrict__ w2t,
                     const float* __restrict__ tnode,
                     float* __restrict__ agg) {
    constexpr int DD = DIN * DOUT;
    constexpr int NCH = DD / 32;            // 32-col chunks
    constexpr int NO = DOUT / 4;            // o-slots per thread (8 or 4)
    constexpr int ASZ = 128 * PK * 2;       // per A image (34816)
    constexpr int BHALF = 32 * PK * 2;      // 8704 B per split per chunk
    constexpr int BSZ = 2 * BHALF;          // 17408
    const int LOQ = DD * PK * 2;            // lo-image offset in w2t

    extern __shared__ char shb[];
    uint8_t* A_hi = (uint8_t*)shb;
    uint8_t* A_lo = A_hi + ASZ;
    uint8_t* Bbuf0 = A_lo + ASZ;
    uint8_t* Bbuf1 = Bbuf0 + BSZ;
    uint8_t* Bbuf2 = A_lo;                  // overlays A_lo (dead after hoist)
    // prologue overlays inside Bbuf0 (8.5KB < 17.4KB)
    float* sea = (float*)Bbuf0;
    float* sw1 = sea + 1024;
    float* sb1 = sw1 + 1024;

    const int tid = threadIdx.x;
    const int lane = tid & 31, warp = tid >> 5;
    const int e0 = blockIdx.x * 128;

    // ---- prologue staging ----
    for (int i = tid; i < 1024; i += 256) sw1[i] = w1[i];
    if (tid < 128) sb1[tid] = b1[tid];
    for (int i = tid; i < 1024; i += 256) {
        long long g = (long long)e0 * 8 + i;
        sea[i] = (g < (long long)KE * 8) ? ea[g] : 0.f;
    }
    __syncthreads();

    // ---- edge MLP (FFMA2 k-pairs) -> split bf16 A images ----
    for (int idx = tid; idx < 8192; idx += 256) {
        int e = idx >> 6, kp = (idx & 63) * 2;
        unsigned long long s2 = pack2(sb1[kp], sb1[kp + 1]);
#pragma unroll
        for (int j = 0; j < 8; j++) {
            float ev = sea[e * 8 + j];
            unsigned long long w2p = *(const unsigned long long*)(sw1 + j * 128 + kp);
            s2 = ffma2(pack2(ev, ev), w2p, s2);
        }
        float s0, s1;
        unpack2(s2, s0, s1);
        s0 = fmaxf(s0, 0.f);
        s1 = fmaxf(s1, 0.f);
        __nv_bfloat16 h0 = __float2bfloat16(s0);
        __nv_bfloat16 h1 = __float2bfloat16(s1);
        __nv_bfloat16 l0 = __float2bfloat16(s0 - __bfloat162float(h0));
        __nv_bfloat16 l1 = __float2bfloat16(s1 - __bfloat162float(h1));
        uint32_t hp = (uint32_t)*(uint16_t*)&h0 | ((uint32_t)*(uint16_t*)&h1 << 16);
        uint32_t lp = (uint32_t)*(uint16_t*)&l0 | ((uint32_t)*(uint16_t*)&l1 << 16);
        int off = (e * PK + kp) * 2;
        *(uint32_t*)(A_hi + off) = hp;
        *(uint32_t*)(A_lo + off) = lp;
    }
    __syncthreads();   // overlays dead; A images ready; Bbuf0/1 free

    // ---- prefetch B chunks 0 and 1 (real buffers only; A_lo still live) ----
    {
        uint32_t s0 = (uint32_t)__cvta_generic_to_shared(Bbuf0);
        for (int j = tid; j < BHALF / 16; j += 256) {
            cp_async16(s0 + j * 16, w2t + j * 16);
            cp_async16(s0 + BHALF + j * 16, w2t + LOQ + j * 16);
        }
        cp_commit();
        uint32_t s1 = (uint32_t)__cvta_generic_to_shared(Bbuf1);
        for (int j = tid; j < BHALF / 16; j += 256) {
            cp_async16(s1 + j * 16, w2t + BHALF + j * 16);
            cp_async16(s1 + BHALF + j * 16, w2t + LOQ + BHALF + j * 16);
        }
        cp_commit();
    }

    // ---- per-thread edge registers ----
    const int gr = lane >> 2;          // 0..7
    const int c2 = (lane & 3) * 2;     // 0,2,4,6
    const int rA = warp * 16 + gr;
    const int ge0 = e0 + rA, ge1 = e0 + rA + 8;
    const bool a0 = ge0 < KE, a1 = ge1 < KE;
    const int sv0 = a0 ? src[ge0] : 0;
    const int sv1 = a1 ? src[ge1] : 0;
    const int dv0 = a0 ? dst[ge0] : 0;
    const int dv1 = a1 ? dst[ge1] : 0;
    const float* x0p = xin + (long long)sv0 * DIN;
    const float* x1p = xin + (long long)sv1 * DIN;

    // ldmatrix lane offsets
    const int gg = lane >> 3, rr = lane & 7;
    const uint32_t bOffNp0 = (uint32_t)((((gg >> 1) * 8 + rr) * PK + (gg & 1) * 8) * 2);
    const uint32_t bOffNp1 = bOffNp0 + (uint32_t)(16 * PK * 2);
    const uint32_t aOff =
        (uint32_t)(((warp * 16 + (lane & 15)) * PK + (lane >> 4) * 8) * 2);

    // ---- hoist chunk-invariant A fragments via LDSM ----
    const uint32_t ahu = (uint32_t)__cvta_generic_to_shared(A_hi);
    const uint32_t alu = (uint32_t)__cvta_generic_to_shared(A_lo);
    uint32_t ahr[8][4], alr[8][4];
#pragma unroll
    for (int k16 = 0; k16 < 8; k16++) {
        ldmx4(ahr[k16], ahu + aOff + k16 * 32);
        ldmx4(alr[k16], alu + aOff + k16 * 32);
    }

    const uint32_t bu[3] = {(uint32_t)__cvta_generic_to_shared(Bbuf0),
                            (uint32_t)__cvta_generic_to_shared(Bbuf1),
                            (uint32_t)__cvta_generic_to_shared(Bbuf2)};

    float msg[2][NO];
#pragma unroll
    for (int p = 0; p < 2; p++)
#pragma unroll
        for (int s = 0; s < NO; s++) msg[p][s] = 0.f;

    int bidx = 0;   // nc % 3
    for (int nc = 0; nc < NCH; nc++) {
        cp_wait1();        // own groups: chunk nc complete (nc+1 may be in flight)
        __syncthreads();   // (a) chunk nc visible from all threads' copies
                           // (b) all warps done reading chunk nc-1's buffer
                           // (c) first iter: A hoist done -> A_lo overlay safe

        // prefetch chunk nc+2 into the buffer read at nc-1 (safe post-barrier)
        if (nc + 2 < NCH) {
            int tb = bidx + 2; if (tb >= 3) tb -= 3;
            uint32_t sb = bu[tb];
            const uint8_t* gh = w2t + (long long)(nc + 2) * BHALF;
            const uint8_t* gl = w2t + LOQ + (long long)(nc + 2) * BHALF;
            for (int j = tid; j < BHALF / 16; j += 256) {
                cp_async16(sb + j * 16, gh + j * 16);
                cp_async16(sb + BHALF + j * 16, gl + j * 16);
            }
        }
        cp_commit();       // uniform group accounting

        const uint32_t bcur = bu[bidx];

        float d[4][4];
#pragma unroll
        for (int n8 = 0; n8 < 4; n8++)
#pragma unroll
            for (int q = 0; q < 4; q++) d[n8][q] = 0.f;

#pragma unroll
        for (int k16 = 0; k16 < 8; k16++) {
            const uint32_t kb2 = k16 * 32;
            uint32_t b0[4], b1[4];
            ldmx4(b0, bcur + bOffNp0 + kb2);
            ldmx4(b1, bcur + bOffNp1 + kb2);
            mma16816(d[0], ahr[k16], b0);
            mma16816(d[0], alr[k16], b0);
            mma16816(d[1], ahr[k16], b0 + 2);
            mma16816(d[1], alr[k16], b0 + 2);
            mma16816(d[2], ahr[k16], b1);
            mma16816(d[2], alr[k16], b1);
            mma16816(d[3], ahr[k16], b1 + 2);
            mma16816(d[3], alr[k16], b1 + 2);
            ldmx4(b0, bcur + BHALF + bOffNp0 + kb2);
            ldmx4(b1, bcur + BHALF + bOffNp1 + kb2);
            mma16816(d[0], ahr[k16], b0);
            mma16816(d[1], ahr[k16], b0 + 2);
            mma16816(d[2], ahr[k16], b1);
            mma16816(d[3], ahr[k16], b1 + 2);
        }

        // ---- fold with x (LDG, L1-hot; 1-2 i values per chunk) ----
        if (DOUT == 32) {
            float xa = x0p[nc];
            float xb = x1p[nc];
#pragma unroll
            for (int n8 = 0; n8 < 4; n8++) {
                msg[0][n8 * 2]     += xa * d[n8][0];
                msg[0][n8 * 2 + 1] += xa * d[n8][1];
                msg[1][n8 * 2]     += xb * d[n8][2];
                msg[1][n8 * 2 + 1] += xb * d[n8][3];
            }
        } else {  // DOUT == 16
            float xa0 = x0p[nc * 2], xa1 = x0p[nc * 2 + 1];
            float xb0 = x1p[nc * 2], xb1 = x1p[nc * 2 + 1];
#pragma unroll
            for (int n8 = 0; n8 < 4; n8++) {
                float xa = (n8 < 2) ? xa0 : xa1;
                float xb = (n8 < 2) ? xb0 : xb1;
                int slot = (n8 & 1) * 2;
                msg[0][slot]     += xa * d[n8][0];
                msg[0][slot + 1] += xa * d[n8][1];
                msg[1][slot]     += xb * d[n8][2];
                msg[1][slot + 1] += xb * d[n8][3];
            }
        }

        if (++bidx == 3) bidx = 0;
    }

    // ---- scatter: single owner per (e,o); add per-node x@b2 term ----
    if (a0) {
        const float* tn = tnode + (long long)sv0 * DOUT;
        float* ap = agg + (long long)dv0 * DOUT;
#pragma unroll
        for (int s = 0; s < NO; s++) {
            int o = (s >> 1) * 8 + c2 + (s & 1);
            atomicAdd(ap + o, msg[0][s] + tn[o]);
        }
    }
    if (a1) {
        const float* tn = tnode + (long long)sv1 * DOUT;
        float* ap = agg + (long long)dv1 * DOUT;
#pragma unroll
        for (int s = 0; s < NO; s++) {
            int o = (s >> 1) * 8 + c2 + (s & 1);
            atomicAdd(ap + o, msg[1][s] + tn[o]);
        }
    }
}

// ---------------- node epilogue: mean + root GEMM + bias (+relu) ----------------
template <int DIN, int DOUT, bool MEAN, bool RELU>
__global__ __launch_bounds__(256)
void node_kernel(const float* __restrict__ xin, const float* __restrict__ agg,
                 const float* __restrict__ root, const float* __restrict__ bias,
                 const int* __restrict__ deg, float* __restrict__ out) {
    __shared__ float sroot[DIN * DOUT];
    __shared__ float sbias[DOUT];
    int tid = threadIdx.x;
    for (int i = tid; i < DIN * DOUT; i += 256) sroot[i] = root[i];
    if (tid < DOUT) sbias[tid] = bias[tid];
    __syncthreads();
    int idx = blockIdx.x * 256 + tid;
    if (idx >= KN * DOUT) return;
    int n = idx / DOUT, o = idx % DOUT;
    float v = agg[idx];
    if (MEAN) {
        int d = deg[n];
        v *= 1.f / (d > 0 ? (float)d : 1.f);
    }
    const float* xr = xin + n * DIN;
#pragma unroll
    for (int i = 0; i < DIN; i++) v = fmaf(xr[i], sroot[i * DOUT + o], v);
    v += sbias[o];
    if (RELU) v = fmaxf(v, 0.f);
    out[idx] = v;
}

// ---------------- launch ----------------
static constexpr int smem_mma() {
    return 2 * (128 * PK * 2) + 2 * (2 * 32 * PK * 2);  // 104,448
}

extern "C" void kernel_launch(void* const* d_in, const int* in_sizes, int n_in,
                              void* d_out, int out_size) {
    const float* x = (const float*)d_in[0];
    const int* ei = (const int*)d_in[1];  // int32 (JAX x64-disabled downcast)
    const float* ea = (const float*)d_in[2];
    auto f = [&](int i) { return (const float*)d_in[i]; };
    float* out = (float*)d_out;
    const int* src = ei;
    const int* dstp = ei + KE;

    void *agg_p, *deg_p, *h1_p, *h2_p, *t_p, *wc1, *wc2, *wmu, *wlv;
    cudaGetSymbolAddress(&agg_p, g_agg);
    cudaGetSymbolAddress(&deg_p, g_deg);
    cudaGetSymbolAddress(&h1_p, g_h1);
    cudaGetSymbolAddress(&h2_p, g_h2);
    cudaGetSymbolAddress(&t_p, g_t);
    cudaGetSymbolAddress(&wc1, g_w2t_c1);
    cudaGetSymbolAddress(&wc2, g_w2t_c2);
    cudaGetSymbolAddress(&wmu, g_w2t_mu);
    cudaGetSymbolAddress(&wlv, g_w2t_lv);

    cudaFuncSetAttribute(edge_mma_kernel<16, 32>,
                         cudaFuncAttributeMaxDynamicSharedMemorySize, smem_mma());
    cudaFuncSetAttribute(edge_mma_kernel<32, 32>,
                         cudaFuncAttributeMaxDynamicSharedMemorySize, smem_mma());
    cudaFuncSetAttribute(edge_mma_kernel<32, 16>,
                         cudaFuncAttributeMaxDynamicSharedMemorySize, smem_mma());

    const int TB = (KE + 127) / 128;
    const int ZB32 = (KN * 32 / 4 + 255) / 256;
    const int ZB16 = (KN * 16 / 4 + 255) / 256;
    const int NB32 = (KN * 32 + 255) / 256;
    const int NB16 = (KN * 16 + 255) / 256;

    // prep w2 images (in-graph, deterministic)
    prep_w2_kernel<<<(512 * 128 + 255) / 256, 256>>>(f(5), 512, (uint8_t*)wc1);
    prep_w2_kernel<<<(1024 * 128 + 255) / 256, 256>>>(f(11), 1024, (uint8_t*)wc2);
    prep_w2_kernel<<<(512 * 128 + 255) / 256, 256>>>(f(17), 512, (uint8_t*)wmu);
    prep_w2_kernel<<<(512 * 128 + 255) / 256, 256>>>(f(23), 512, (uint8_t*)wlv);

    zero_i_kernel<<<(KN + 255) / 256, 256>>>((int*)deg_p, KN);
    deg_kernel<<<(KE + 255) / 256, 256>>>(dstp);

    // conv1: 16 -> 32, mean, relu
    zero_f_kernel<<<ZB32, 256>>>((float*)agg_p, KN * 32);
    xb2_kernel<16, 32><<<NB32, 256>>>(x, f(6), (float*)t_p);
    edge_mma_kernel<16, 32><<<TB, 256, smem_mma()>>>(
        x, ea, src, dstp, f(3), f(4), (const uint8_t*)wc1, (const float*)t_p,
        (float*)agg_p);
    node_kernel<16, 32, true, true><<<NB32, 256>>>(
        x, (const float*)agg_p, f(7), f(8), (const int*)deg_p, (float*)h1_p);

    // conv2: 32 -> 32, mean, relu
    zero_f_kernel<<<ZB32, 256>>>((float*)agg_p, KN * 32);
    xb2_kernel<32, 32><<<NB32, 256>>>((const float*)h1_p, f(12), (float*)t_p);
    edge_mma_kernel<32, 32><<<TB, 256, smem_mma()>>>(
        (const float*)h1_p, ea, src, dstp, f(9), f(10), (const uint8_t*)wc2,
        (const float*)t_p, (float*)agg_p);
    node_kernel<32, 32, true, true><<<NB32, 256>>>(
        (const float*)h1_p, (const float*)agg_p, f(13), f(14), (const int*)deg_p,
        (float*)h2_p);

    // mu: 32 -> 16, sum
    zero_f_kernel<<<ZB16, 256>>>((float*)agg_p, KN * 16);
    xb2_kernel<32, 16><<<NB16, 256>>>((const float*)h2_p, f(18), (float*)t_p);
    edge_mma_kernel<32, 16><<<TB, 256, smem_mma()>>>(
        (const float*)h2_p, ea, src, dstp, f(15), f(16), (const uint8_t*)wmu,
        (const float*)t_p, (float*)agg_p);
    node_kernel<32, 16, false, false><<<NB16, 256>>>(
        (const float*)h2_p, (const float*)agg_p, f(19), f(20), (const int*)deg_p,
        out);

    // logvar: 32 -> 16, sum
    zero_f_kernel<<<ZB16, 256>>>((float*)agg_p, KN * 16);
    xb2_kernel<32, 16><<<NB16, 256>>>((const float*)h2_p, f(24), (float*)t_p);
    edge_mma_kernel<32, 16><<<TB, 256, smem_mma()>>>(
        (const float*)h2_p, ea, src, dstp, f(21), f(22), (const uint8_t*)wlv,
        (const float*)t_p, (float*)agg_p);
    node_kernel<32, 16, false, false><<<NB16, 256>>>(
        (const float*)h2_p, (const float*)agg_p, f(25), f(26), (const int*)deg_p,
        out + KN * 16);
}

// round 16
// speedup vs baseline: 1.2753x; 1.1966x over previous
#include <cuda_runtime.h>
#include <cuda_bf16.h>
#include <cuda_fp16.h>
#include <cstdint>

// Problem constants
static constexpr int KN = 50000;   // nodes
static constexpr int KE = 150000;  // edges
// dims: IN=16, HID=32, LAT=16, EF=8, HE=128
static constexpr int PK = 136;     // fp16 pitch for [n][k] / [e][k] tiles

// ---------------- device scratch (static, no allocation) ----------------
__device__ __align__(16) float g_agg[KN * 32];
__device__ __align__(16) float g_h1[KN * 32];
__device__ __align__(16) float g_h2[KN * 32];
__device__ __align__(16) float g_t[KN * 32];   // per-node x@b2 term
__device__ __align__(16) int   g_deg[KN];
// prepped w2: [n][PK] fp16, hi image then lo image
__device__ __align__(16) uint8_t g_w2t_c1[512 * PK * 2 * 2];
__device__ __align__(16) uint8_t g_w2t_c2[1024 * PK * 2 * 2];
__device__ __align__(16) uint8_t g_w2t_mu[512 * PK * 2 * 2];
__device__ __align__(16) uint8_t g_w2t_lv[512 * PK * 2 * 2];

// ---------------- helpers ----------------
__device__ __forceinline__ void cp_async16(uint32_t saddr, const void* gptr) {
    asm volatile("cp.async.cg.shared.global [%0], [%1], 16;" ::"r"(saddr), "l"(gptr));
}
__device__ __forceinline__ void cp_commit() { asm volatile("cp.async.commit_group;"); }
__device__ __forceinline__ void cp_wait1() { asm volatile("cp.async.wait_group 1;"); }

__device__ __forceinline__ void mma16816h(float* d, const uint32_t* a,
                                          const uint32_t* b) {
    asm volatile(
        "mma.sync.aligned.m16n8k16.row.col.f32.f16.f16.f32 "
        "{%0,%1,%2,%3}, {%4,%5,%6,%7}, {%8,%9}, {%0,%1,%2,%3};"
        : "+f"(d[0]), "+f"(d[1]), "+f"(d[2]), "+f"(d[3])
        : "r"(a[0]), "r"(a[1]), "r"(a[2]), "r"(a[3]), "r"(b[0]), "r"(b[1]));
}
__device__ __forceinline__ void ldmx4(uint32_t* r, uint32_t addr) {
    asm volatile(
        "ldmatrix.sync.aligned.m8n8.x4.shared.b16 {%0,%1,%2,%3}, [%4];"
        : "=r"(r[0]), "=r"(r[1]), "=r"(r[2]), "=r"(r[3]) : "r"(addr));
}
// f32x2 packed helpers (Blackwell FFMA2)
__device__ __forceinline__ unsigned long long pack2(float x, float y) {
    unsigned long long r;
    asm("mov.b64 %0, {%1, %2};" : "=l"(r) : "f"(x), "f"(y));
    return r;
}
__device__ __forceinline__ void unpack2(unsigned long long v, float& lo, float& hi) {
    asm("mov.b64 {%0, %1}, %2;" : "=f"(lo), "=f"(hi) : "l"(v));
}
__device__ __forceinline__ unsigned long long ffma2(unsigned long long a,
                                                    unsigned long long b,
                                                    unsigned long long c) {
    unsigned long long d;
    asm("fma.rn.f32x2 %0, %1, %2, %3;" : "=l"(d) : "l"(a), "l"(b), "l"(c));
    return d;
}

// ---------------- zeroing / degree ----------------
__global__ void zero_i_kernel(int* __restrict__ p, int n) {
    int i = blockIdx.x * 256 + threadIdx.x;
    if (i < n) p[i] = 0;
}
__global__ void deg_kernel(const int* __restrict__ dst) {
    int i = blockIdx.x * 256 + threadIdx.x;
    if (i < KE) atomicAdd(&g_deg[dst[i]], 1);
}

// ---------------- w2 prep: transpose + fp16 hi/lo split ----------------
__global__ void prep_w2_kernel(const float* __restrict__ w2, int dd,
                               uint8_t* __restrict__ outb) {
    int idx = blockIdx.x * 256 + threadIdx.x;
    if (idx >= dd * 128) return;
    int n = idx >> 7, k = idx & 127;
    float v = w2[k * dd + n];
    __half hi = __float2half(v);
    __half lo = __float2half(v - __half2float(hi));
    int off = (n * PK + k) * 2;
    int loq = dd * PK * 2;
    *(__half*)(outb + off) = hi;
    *(__half*)(outb + loq + off) = lo;
}

// ---------------- per-node x@b2 (+ fused agg zeroing, same index space) ----
template <int DIN, int DOUT>
__global__ __launch_bounds__(256)
void xb2_kernel(const float* __restrict__ xin, const float* __restrict__ b2,
                float* __restrict__ t, float* __restrict__ agg) {
    __shared__ float sb[DIN * DOUT];
    int tid = threadIdx.x;
    for (int i = tid; i < DIN * DOUT; i += 256) sb[i] = b2[i];
    __syncthreads();
    int idx = blockIdx.x * 256 + tid;
    if (idx >= KN * DOUT) return;
    int n = idx / DOUT, o = idx % DOUT;
    float s = 0.f;
#pragma unroll
    for (int i = 0; i < DIN; i++) s = fmaf(xin[n * DIN + i], sb[i * DOUT + o], s);
    t[idx] = s;
    agg[idx] = 0.f;
}

// ---------------- HMMA edge kernel: fp16 2-split, triple-buffered ----------
// 128 edges/block, 8 warps x 16 rows, occ-2. fp16 split keeps hh + h_hi*w_lo
// (drops h_lo*w_hi ~2^-12): 8 MMA + 4 LDSM per k16 (was 12+4 with bf16 3-split).
// A_lo eliminated entirely. One barrier per chunk (triple buffer).
template <int DIN, int DOUT>
__global__ __launch_bounds__(256, 2)
void edge_mma_kernel(const float* __restrict__ xin,
                     const float* __restrict__ ea,
                     const int* __restrict__ src,
                     const int* __restrict__ dst,
                     const float* __restrict__ w1,
                     const float* __restrict__ b1,
                     const uint8_t* __restrict__ w2t,
                     const float* __restrict__ tnode,
                     float* __restrict__ agg) {
    constexpr int DD = DIN * DOUT;
    constexpr int NCH = DD / 32;            // 32-col chunks
    constexpr int NO = DOUT / 4;            // o-slots per thread (8 or 4)
    constexpr int ASZ = 128 * PK * 2;       // A_hi image (34816)
    constexpr int BHALF = 32 * PK * 2;      // 8704 B per split per chunk
    constexpr int BSZ = 2 * BHALF;          // 17408
    const int LOQ = DD * PK * 2;            // lo-image offset in w2t

    extern __shared__ char shb[];
    uint8_t* A_hi = (uint8_t*)shb;
    uint8_t* Bbuf0 = A_hi + ASZ;
    uint8_t* Bbuf1 = Bbuf0 + BSZ;
    uint8_t* Bbuf2 = Bbuf1 + BSZ;
    // prologue overlays inside Bbuf0 (8.5KB < 17.4KB)
    float* sea = (float*)Bbuf0;
    float* sw1 = sea + 1024;
    float* sb1 = sw1 + 1024;

    const int tid = threadIdx.x;
    const int lane = tid & 31, warp = tid >> 5;
    const int e0 = blockIdx.x * 128;

    // ---- prologue staging ----
    for (int i = tid; i < 1024; i += 256) sw1[i] = w1[i];
    if (tid < 128) sb1[tid] = b1[tid];
    for (int i = tid; i < 1024; i += 256) {
        long long g = (long long)e0 * 8 + i;
        sea[i] = (g < (long long)KE * 8) ? ea[g] : 0.f;
    }
    __syncthreads();

    // ---- edge MLP (FFMA2 k-pairs) -> fp16 A_hi image ----
    for (int idx = tid; idx < 8192; idx += 256) {
        int e = idx >> 6, kp = (idx & 63) * 2;
        unsigned long long s2 = pack2(sb1[kp], sb1[kp + 1]);
#pragma unroll
        for (int j = 0; j < 8; j++) {
            float ev = sea[e * 8 + j];
            unsigned long long w2p = *(const unsigned long long*)(sw1 + j * 128 + kp);
            s2 = ffma2(pack2(ev, ev), w2p, s2);
        }
        float s0, s1;
        unpack2(s2, s0, s1);
        s0 = fmaxf(s0, 0.f);
        s1 = fmaxf(s1, 0.f);
        __half h0 = __float2half(s0);
        __half h1 = __float2half(s1);
        uint32_t hp = (uint32_t)*(uint16_t*)&h0 | ((uint32_t)*(uint16_t*)&h1 << 16);
        *(uint32_t*)(A_hi + (e * PK + kp) * 2) = hp;
    }
    __syncthreads();   // overlays dead; A_hi ready; B buffers free

    // ---- prefetch B chunks 0 and 1 ----
    {
        uint32_t s0 = (uint32_t)__cvta_generic_to_shared(Bbuf0);
        for (int j = tid; j < BHALF / 16; j += 256) {
            cp_async16(s0 + j * 16, w2t + j * 16);
            cp_async16(s0 + BHALF + j * 16, w2t + LOQ + j * 16);
        }
        cp_commit();
        uint32_t s1 = (uint32_t)__cvta_generic_to_shared(Bbuf1);
        for (int j = tid; j < BHALF / 16; j += 256) {
            cp_async16(s1 + j * 16, w2t + BHALF + j * 16);
            cp_async16(s1 + BHALF + j * 16, w2t + LOQ + BHALF + j * 16);
        }
        cp_commit();
    }

    // ---- per-thread edge registers ----
    const int gr = lane >> 2;          // 0..7
    const int c2 = (lane & 3) * 2;     // 0,2,4,6
    const int rA = warp * 16 + gr;
    const int ge0 = e0 + rA, ge1 = e0 + rA + 8;
    const bool a0 = ge0 < KE, a1 = ge1 < KE;
    const int sv0 = a0 ? src[ge0] : 0;
    const int sv1 = a1 ? src[ge1] : 0;
    const int dv0 = a0 ? dst[ge0] : 0;
    const int dv1 = a1 ? dst[ge1] : 0;
    const float* x0p = xin + (long long)sv0 * DIN;
    const float* x1p = xin + (long long)sv1 * DIN;

    // ldmatrix lane offsets
    const int gg = lane >> 3, rr = lane & 7;
    const uint32_t bOffNp0 = (uint32_t)((((gg >> 1) * 8 + rr) * PK + (gg & 1) * 8) * 2);
    const uint32_t bOffNp1 = bOffNp0 + (uint32_t)(16 * PK * 2);
    const uint32_t aOff =
        (uint32_t)(((warp * 16 + (lane & 15)) * PK + (lane >> 4) * 8) * 2);

    // ---- hoist chunk-invariant A fragments via LDSM ----
    const uint32_t ahu = (uint32_t)__cvta_generic_to_shared(A_hi);
    uint32_t ahr[8][4];
#pragma unroll
    for (int k16 = 0; k16 < 8; k16++) ldmx4(ahr[k16], ahu + aOff + k16 * 32);

    const uint32_t bu[3] = {(uint32_t)__cvta_generic_to_shared(Bbuf0),
                            (uint32_t)__cvta_generic_to_shared(Bbuf1),
                            (uint32_t)__cvta_generic_to_shared(Bbuf2)};

    float msg[2][NO];
#pragma unroll
    for (int p = 0; p < 2; p++)
#pragma unroll
        for (int s = 0; s < NO; s++) msg[p][s] = 0.f;

    int bidx = 0;   // nc % 3
    for (int nc = 0; nc < NCH; nc++) {
        cp_wait1();        // chunk nc complete (nc+1 may be in flight)
        __syncthreads();   // data visible + previous buffer drained

        // prefetch chunk nc+2 into the buffer read at nc-1
        if (nc + 2 < NCH) {
            int tb = bidx + 2; if (tb >= 3) tb -= 3;
            uint32_t sb = bu[tb];
            const uint8_t* gh = w2t + (long long)(nc + 2) * BHALF;
            const uint8_t* gl = w2t + LOQ + (long long)(nc + 2) * BHALF;
            for (int j = tid; j < BHALF / 16; j += 256) {
                cp_async16(sb + j * 16, gh + j * 16);
                cp_async16(sb + BHALF + j * 16, gl + j * 16);
            }
        }
        cp_commit();       // uniform group accounting

        const uint32_t bcur = bu[bidx];

        float d[4][4];
#pragma unroll
        for (int n8 = 0; n8 < 4; n8++)
#pragma unroll
            for (int q = 0; q < 4; q++) d[n8][q] = 0.f;

#pragma unroll
        for (int k16 = 0; k16 < 8; k16++) {
            const uint32_t kb2 = k16 * 32;
            uint32_t b0[4], b1[4];
            // hi split of w2
            ldmx4(b0, bcur + bOffNp0 + kb2);
            ldmx4(b1, bcur + bOffNp1 + kb2);
            mma16816h(d[0], ahr[k16], b0);
            mma16816h(d[1], ahr[k16], b0 + 2);
            mma16816h(d[2], ahr[k16], b1);
            mma16816h(d[3], ahr[k16], b1 + 2);
            // lo split of w2 (reuse regs)
            ldmx4(b0, bcur + BHALF + bOffNp0 + kb2);
            ldmx4(b1, bcur + BHALF + bOffNp1 + kb2);
            mma16816h(d[0], ahr[k16], b0);
            mma16816h(d[1], ahr[k16], b0 + 2);
            mma16816h(d[2], ahr[k16], b1);
            mma16816h(d[3], ahr[k16], b1 + 2);
        }

        // ---- fold with x (LDG, L1-hot; 1-2 i values per chunk) ----
        if (DOUT == 32) {
            float xa = x0p[nc];
            float xb = x1p[nc];
#pragma unroll
            for (int n8 = 0; n8 < 4; n8++) {
                msg[0][n8 * 2]     += xa * d[n8][0];
                msg[0][n8 * 2 + 1] += xa * d[n8][1];
                msg[1][n8 * 2]     += xb * d[n8][2];
                msg[1][n8 * 2 + 1] += xb * d[n8][3];
            }
        } else {  // DOUT == 16
            float xa0 = x0p[nc * 2], xa1 = x0p[nc * 2 + 1];
            float xb0 = x1p[nc * 2], xb1 = x1p[nc * 2 + 1];
#pragma unroll
            for (int n8 = 0; n8 < 4; n8++) {
                float xa = (n8 < 2) ? xa0 : xa1;
                float xb = (n8 < 2) ? xb0 : xb1;
                int slot = (n8 & 1) * 2;
                msg[0][slot]     += xa * d[n8][0];
                msg[0][slot + 1] += xa * d[n8][1];
                msg[1][slot]     += xb * d[n8][2];
                msg[1][slot + 1] += xb * d[n8][3];
            }
        }

        if (++bidx == 3) bidx = 0;
    }

    // ---- scatter: single owner per (e,o); add per-node x@b2 term ----
    if (a0) {
        const float* tn = tnode + (long long)sv0 * DOUT;
        float* ap = agg + (long long)dv0 * DOUT;
#pragma unroll
        for (int s = 0; s < NO; s++) {
            int o = (s >> 1) * 8 + c2 + (s & 1);
            atomicAdd(ap + o, msg[0][s] + tn[o]);
        }
    }
    if (a1) {
        const float* tn = tnode + (long long)sv1 * DOUT;
        float* ap = agg + (long long)dv1 * DOUT;
#pragma unroll
        for (int s = 0; s < NO; s++) {
            int o = (s >> 1) * 8 + c2 + (s & 1);
            atomicAdd(ap + o, msg[1][s] + tn[o]);
        }
    }
}

// ---------------- node epilogue: mean + root GEMM + bias (+relu) ----------------
template <int DIN, int DOUT, bool MEAN, bool RELU>
__global__ __launch_bounds__(256)
void node_kernel(const float* __restrict__ xin, const float* __restrict__ agg,
                 const float* __restrict__ root, const float* __restrict__ bias,
                 const int* __restrict__ deg, float* __restrict__ out) {
    __shared__ float sroot[DIN * DOUT];
    __shared__ float sbias[DOUT];
    int tid = threadIdx.x;
    for (int i = tid; i < DIN * DOUT; i += 256) sroot[i] = root[i];
    if (tid < DOUT) sbias[tid] = bias[tid];
    __syncthreads();
    int idx = blockIdx.x * 256 + tid;
    if (idx >= KN * DOUT) return;
    int n = idx / DOUT, o = idx % DOUT;
    float v = agg[idx];
    if (MEAN) {
        int d = deg[n];
        v *= 1.f / (d > 0 ? (float)d : 1.f);
    }
    const float* xr = xin + n * DIN;
#pragma unroll
    for (int i = 0; i < DIN; i++) v = fmaf(xr[i], sroot[i * DOUT + o], v);
    v += sbias[o];
    if (RELU) v = fmaxf(v, 0.f);
    out[idx] = v;
}

// ---------------- launch ----------------
static constexpr int smem_mma() {
    return 128 * PK * 2 + 3 * (2 * 32 * PK * 2);  // 34816 + 52224 = 87040
}

extern "C" void kernel_launch(void* const* d_in, const int* in_sizes, int n_in,
                              void* d_out, int out_size) {
    const float* x = (const float*)d_in[0];
    const int* ei = (const int*)d_in[1];  // int32 (JAX x64-disabled downcast)
    const float* ea = (const float*)d_in[2];
    auto f = [&](int i) { return (const float*)d_in[i]; };
    float* out = (float*)d_out;
    const int* src = ei;
    const int* dstp = ei + KE;

    void *agg_p, *deg_p, *h1_p, *h2_p, *t_p, *wc1, *wc2, *wmu, *wlv;
    cudaGetSymbolAddress(&agg_p, g_agg);
    cudaGetSymbolAddress(&deg_p, g_deg);
    cudaGetSymbolAddress(&h1_p, g_h1);
    cudaGetSymbolAddress(&h2_p, g_h2);
    cudaGetSymbolAddress(&t_p, g_t);
    cudaGetSymbolAddress(&wc1, g_w2t_c1);
    cudaGetSymbolAddress(&wc2, g_w2t_c2);
    cudaGetSymbolAddress(&wmu, g_w2t_mu);
    cudaGetSymbolAddress(&wlv, g_w2t_lv);

    cudaFuncSetAttribute(edge_mma_kernel<16, 32>,
                         cudaFuncAttributeMaxDynamicSharedMemorySize, smem_mma());
    cudaFuncSetAttribute(edge_mma_kernel<32, 32>,
                         cudaFuncAttributeMaxDynamicSharedMemorySize, smem_mma());
    cudaFuncSetAttribute(edge_mma_kernel<32, 16>,
                         cudaFuncAttributeMaxDynamicSharedMemorySize, smem_mma());

    const int TB = (KE + 127) / 128;
    const int NB32 = (KN * 32 + 255) / 256;
    const int NB16 = (KN * 16 + 255) / 256;

    // prep w2 images (in-graph, deterministic)
    prep_w2_kernel<<<(512 * 128 + 255) / 256, 256>>>(f(5), 512, (uint8_t*)wc1);
    prep_w2_kernel<<<(1024 * 128 + 255) / 256, 256>>>(f(11), 1024, (uint8_t*)wc2);
    prep_w2_kernel<<<(512 * 128 + 255) / 256, 256>>>(f(17), 512, (uint8_t*)wmu);
    prep_w2_kernel<<<(512 * 128 + 255) / 256, 256>>>(f(23), 512, (uint8_t*)wlv);

    zero_i_kernel<<<(KN + 255) / 256, 256>>>((int*)deg_p, KN);
    deg_kernel<<<(KE + 255) / 256, 256>>>(dstp);

    // conv1: 16 -> 32, mean, relu  (xb2 also zeroes agg)
    xb2_kernel<16, 32><<<NB32, 256>>>(x, f(6), (float*)t_p, (float*)agg_p);
    edge_mma_kernel<16, 32><<<TB, 256, smem_mma()>>>(
        x, ea, src, dstp, f(3), f(4), (const uint8_t*)wc1, (const float*)t_p,
        (float*)agg_p);
    node_kernel<16, 32, true, true><<<NB32, 256>>>(
        x, (const float*)agg_p, f(7), f(8), (const int*)deg_p, (float*)h1_p);

    // conv2: 32 -> 32, mean, relu
    xb2_kernel<32, 32><<<NB32, 256>>>((const float*)h1_p, f(12), (float*)t_p,
                                      (float*)agg_p);
    edge_mma_kernel<32, 32><<<TB, 256, smem_mma()>>>(
        (const float*)h1_p, ea, src, dstp, f(9), f(10), (const uint8_t*)wc2,
        (const float*)t_p, (float*)agg_p);
    node_kernel<32, 32, true, true><<<NB32, 256>>>(
        (const float*)h1_p, (const float*)agg_p, f(13), f(14), (const int*)deg_p,
        (float*)h2_p);

    // mu: 32 -> 16, sum
    xb2_kernel<32, 16><<<NB16, 256>>>((const float*)h2_p, f(18), (float*)t_p,
                                      (float*)agg_p);
    edge_mma_kernel<32, 16><<<TB, 256, smem_mma()>>>(
        (const float*)h2_p, ea, src, dstp, f(15), f(16), (const uint8_t*)wmu,
        (const float*)t_p, (float*)agg_p);
    node_kernel<32, 16, false, false><<<NB16, 256>>>(
        (const float*)h2_p, (const float*)agg_p, f(19), f(20), (const int*)deg_p,
        out);

    // logvar: 32 -> 16, sum
    xb2_kernel<32, 16><<<NB16, 256>>>((const float*)h2_p, f(24), (float*)t_p,
                                      (float*)agg_p);
    edge_mma_kernel<32, 16><<<TB, 256, smem_mma()>>>(
        (const float*)h2_p, ea, src, dstp, f(21), f(22), (const uint8_t*)wlv,
        (const float*)t_p, (float*)agg_p);
    node_kernel<32, 16, false, false><<<NB16, 256>>>(
        (const float*)h2_p, (const float*)agg_p, f(25), f(26), (const int*)deg_p,
        out + KN * 16);
}

// round 17
// speedup vs baseline: 1.7164x; 1.3459x over previous
#include <cuda_runtime.h>
#include <cuda_bf16.h>
#include <cuda_fp16.h>
#include <cstdint>

// Problem constants
static constexpr int KN = 50000;   // nodes
static constexpr int KE = 150000;  // edges
// dims: IN=16, HID=32, LAT=16, EF=8, HE=128
static constexpr int PK = 136;     // fp16 pitch for [n][k] / [e][k] tiles

// ---------------- device scratch (static, no allocation) ----------------
__device__ __align__(16) float g_agg[KN * 32];
__device__ __align__(16) float g_h1[KN * 32];
__device__ __align__(16) float g_h2[KN * 32];
__device__ __align__(16) float g_t[KN * 32];   // per-node x@b2 term
__device__ __align__(16) int   g_deg[KN];
// prepped w2: [n][PK] fp16 hi image (single-GEMM path reads hi only)
__device__ __align__(16) uint8_t g_w2t_c1[512 * PK * 2];
__device__ __align__(16) uint8_t g_w2t_c2[1024 * PK * 2];
__device__ __align__(16) uint8_t g_w2t_mu[512 * PK * 2];
__device__ __align__(16) uint8_t g_w2t_lv[512 * PK * 2];

// ---------------- helpers ----------------
__device__ __forceinline__ void cp_async16(uint32_t saddr, const void* gptr) {
    asm volatile("cp.async.cg.shared.global [%0], [%1], 16;" ::"r"(saddr), "l"(gptr));
}
__device__ __forceinline__ void cp_commit() { asm volatile("cp.async.commit_group;"); }
__device__ __forceinline__ void cp_wait1() { asm volatile("cp.async.wait_group 1;"); }

__device__ __forceinline__ void mma16816h(float* d, const uint32_t* a,
                                          const uint32_t* b) {
    asm volatile(
        "mma.sync.aligned.m16n8k16.row.col.f32.f16.f16.f32 "
        "{%0,%1,%2,%3}, {%4,%5,%6,%7}, {%8,%9}, {%0,%1,%2,%3};"
        : "+f"(d[0]), "+f"(d[1]), "+f"(d[2]), "+f"(d[3])
        : "r"(a[0]), "r"(a[1]), "r"(a[2]), "r"(a[3]), "r"(b[0]), "r"(b[1]));
}
__device__ __forceinline__ void ldmx4(uint32_t* r, uint32_t addr) {
    asm volatile(
        "ldmatrix.sync.aligned.m8n8.x4.shared.b16 {%0,%1,%2,%3}, [%4];"
        : "=r"(r[0]), "=r"(r[1]), "=r"(r[2]), "=r"(r[3]) : "r"(addr));
}
// f32x2 packed helpers (Blackwell FFMA2)
__device__ __forceinline__ unsigned long long pack2(float x, float y) {
    unsigned long long r;
    asm("mov.b64 %0, {%1, %2};" : "=l"(r) : "f"(x), "f"(y));
    return r;
}
__device__ __forceinline__ void unpack2(unsigned long long v, float& lo, float& hi) {
    asm("mov.b64 {%0, %1}, %2;" : "=f"(lo), "=f"(hi) : "l"(v));
}
__device__ __forceinline__ unsigned long long ffma2(unsigned long long a,
                                                    unsigned long long b,
                                                    unsigned long long c) {
    unsigned long long d;
    asm("fma.rn.f32x2 %0, %1, %2, %3;" : "=l"(d) : "l"(a), "l"(b), "l"(c));
    return d;
}

// ---------------- zeroing / degree ----------------
__global__ void zero_i_kernel(int* __restrict__ p, int n) {
    int i = blockIdx.x * 256 + threadIdx.x;
    if (i < n) p[i] = 0;
}
__global__ void deg_kernel(const int* __restrict__ dst) {
    int i = blockIdx.x * 256 + threadIdx.x;
    if (i < KE) atomicAdd(&g_deg[dst[i]], 1);
}

// ---------------- w2 prep: transpose + fp16 (hi only) ----------------
__global__ void prep_w2_kernel(const float* __restrict__ w2, int dd,
                               uint8_t* __restrict__ outb) {
    int idx = blockIdx.x * 256 + threadIdx.x;
    if (idx >= dd * 128) return;
    int n = idx >> 7, k = idx & 127;
    float v = w2[k * dd + n];
    *(__half*)(outb + (n * PK + k) * 2) = __float2half(v);
}

// ---------------- per-node x@b2 (+ fused agg zeroing) ----------------
template <int DIN, int DOUT>
__global__ __launch_bounds__(256)
void xb2_kernel(const float* __restrict__ xin, const float* __restrict__ b2,
                float* __restrict__ t, float* __restrict__ agg) {
    __shared__ float sb[DIN * DOUT];
    int tid = threadIdx.x;
    for (int i = tid; i < DIN * DOUT; i += 256) sb[i] = b2[i];
    __syncthreads();
    int idx = blockIdx.x * 256 + tid;
    if (idx >= KN * DOUT) return;
    int n = idx / DOUT, o = idx % DOUT;
    float s = 0.f;
#pragma unroll
    for (int i = 0; i < DIN; i++) s = fmaf(xin[n * DIN + i], sb[i * DOUT + o], s);
    t[idx] = s;
    agg[idx] = 0.f;
}

// ---------------- HMMA edge kernel: single fp16 GEMM, 64-col chunks --------
// 128 edges/block, 8 warps x 16 rows, occ-2. Single h_hi x w_hi GEMM
// (dropped terms each ~2^-12; calibrated total rel_err ~3e-4 < 1e-3).
// Chunk = 64 cols (17.4KB), triple-buffered, 1 barrier per chunk.
// Per k16: 4 LDSM + 8 MMA covering 64 cols.
template <int DIN, int DOUT>
__global__ __launch_bounds__(256, 2)
void edge_mma_kernel(const float* __restrict__ xin,
                     const float* __restrict__ ea,
                     const int* __restrict__ src,
                     const int* __restrict__ dst,
                     const float* __restrict__ w1,
                     const float* __restrict__ b1,
                     const uint8_t* __restrict__ w2t,
                     const float* __restrict__ tnode,
                     float* __restrict__ agg) {
    constexpr int DD = DIN * DOUT;
    constexpr int NCH = DD / 64;            // 64-col chunks
    constexpr int NO = DOUT / 4;            // o-slots per thread (8 or 4)
    constexpr int ASZ = 128 * PK * 2;       // A_hi image (34816)
    constexpr int BCH = 64 * PK * 2;        // 17408 B per chunk (hi only)

    extern __shared__ char shb[];
    uint8_t* A_hi = (uint8_t*)shb;
    uint8_t* Bbuf0 = A_hi + ASZ;
    uint8_t* Bbuf1 = Bbuf0 + BCH;
    uint8_t* Bbuf2 = Bbuf1 + BCH;
    // prologue overlays inside Bbuf0 (8.5KB < 17.4KB)
    float* sea = (float*)Bbuf0;
    float* sw1 = sea + 1024;
    float* sb1 = sw1 + 1024;

    const int tid = threadIdx.x;
    const int lane = tid & 31, warp = tid >> 5;
    const int e0 = blockIdx.x * 128;

    // ---- prologue staging ----
    for (int i = tid; i < 1024; i += 256) sw1[i] = w1[i];
    if (tid < 128) sb1[tid] = b1[tid];
    for (int i = tid; i < 1024; i += 256) {
        long long g = (long long)e0 * 8 + i;
        sea[i] = (g < (long long)KE * 8) ? ea[g] : 0.f;
    }
    __syncthreads();

    // ---- edge MLP (FFMA2 k-pairs) -> fp16 A_hi image ----
    for (int idx = tid; idx < 8192; idx += 256) {
        int e = idx >> 6, kp = (idx & 63) * 2;
        unsigned long long s2 = pack2(sb1[kp], sb1[kp + 1]);
#pragma unroll
        for (int j = 0; j < 8; j++) {
            float ev = sea[e * 8 + j];
            unsigned long long w2p = *(const unsigned long long*)(sw1 + j * 128 + kp);
            s2 = ffma2(pack2(ev, ev), w2p, s2);
        }
        float s0, s1;
        unpack2(s2, s0, s1);
        s0 = fmaxf(s0, 0.f);
        s1 = fmaxf(s1, 0.f);
        __half h0 = __float2half(s0);
        __half h1 = __float2half(s1);
        uint32_t hp = (uint32_t)*(uint16_t*)&h0 | ((uint32_t)*(uint16_t*)&h1 << 16);
        *(uint32_t*)(A_hi + (e * PK + kp) * 2) = hp;
    }
    __syncthreads();   // overlays dead; A_hi ready; B buffers free

    // ---- prefetch B chunks 0 and 1 ----
    {
        uint32_t s0 = (uint32_t)__cvta_generic_to_shared(Bbuf0);
        for (int j = tid; j < BCH / 16; j += 256)
            cp_async16(s0 + j * 16, w2t + j * 16);
        cp_commit();
        uint32_t s1 = (uint32_t)__cvta_generic_to_shared(Bbuf1);
        for (int j = tid; j < BCH / 16; j += 256)
            cp_async16(s1 + j * 16, w2t + BCH + j * 16);
        cp_commit();
    }

    // ---- per-thread edge registers ----
    const int gr = lane >> 2;          // 0..7
    const int c2 = (lane & 3) * 2;     // 0,2,4,6
    const int rA = warp * 16 + gr;
    const int ge0 = e0 + rA, ge1 = e0 + rA + 8;
    const bool a0 = ge0 < KE, a1 = ge1 < KE;
    const int sv0 = a0 ? src[ge0] : 0;
    const int sv1 = a1 ? src[ge1] : 0;
    const int dv0 = a0 ? dst[ge0] : 0;
    const int dv1 = a1 ? dst[ge1] : 0;
    const float* x0p = xin + (long long)sv0 * DIN;
    const float* x1p = xin + (long long)sv1 * DIN;

    // ldmatrix lane offsets (base covers n8 pair {0,1}; +g*16 rows per pair g)
    const int gg = lane >> 3, rr = lane & 7;
    const uint32_t bOff0 = (uint32_t)((((gg >> 1) * 8 + rr) * PK + (gg & 1) * 8) * 2);
    const uint32_t aOff =
        (uint32_t)(((warp * 16 + (lane & 15)) * PK + (lane >> 4) * 8) * 2);

    // ---- hoist chunk-invariant A fragments via LDSM ----
    const uint32_t ahu = (uint32_t)__cvta_generic_to_shared(A_hi);
    uint32_t ahr[8][4];
#pragma unroll
    for (int k16 = 0; k16 < 8; k16++) ldmx4(ahr[k16], ahu + aOff + k16 * 32);

    const uint32_t bu[3] = {(uint32_t)__cvta_generic_to_shared(Bbuf0),
                            (uint32_t)__cvta_generic_to_shared(Bbuf1),
                            (uint32_t)__cvta_generic_to_shared(Bbuf2)};

    float msg[2][NO];
#pragma unroll
    for (int p = 0; p < 2; p++)
#pragma unroll
        for (int s = 0; s < NO; s++) msg[p][s] = 0.f;

    int bidx = 0;   // nc % 3
    for (int nc = 0; nc < NCH; nc++) {
        cp_wait1();        // chunk nc complete (nc+1 may be in flight)
        __syncthreads();   // data visible + previous buffer drained

        // prefetch chunk nc+2 into the buffer read at nc-1
        if (nc + 2 < NCH) {
            int tb = bidx + 2; if (tb >= 3) tb -= 3;
            uint32_t sb = bu[tb];
            const uint8_t* gsrc = w2t + (long long)(nc + 2) * BCH;
            for (int j = tid; j < BCH / 16; j += 256)
                cp_async16(sb + j * 16, gsrc + j * 16);
        }
        cp_commit();       // uniform group accounting

        const uint32_t bcur = bu[bidx];

        float d[8][4];
#pragma unroll
        for (int n8 = 0; n8 < 8; n8++)
#pragma unroll
            for (int q = 0; q < 4; q++) d[n8][q] = 0.f;

#pragma unroll
        for (int k16 = 0; k16 < 8; k16++) {
            const uint32_t kb2 = k16 * 32;
#pragma unroll
            for (int g = 0; g < 4; g++) {   // n8 pair g -> rows g*16..g*16+15
                uint32_t b[4];
                ldmx4(b, bcur + bOff0 + (uint32_t)(g * 16 * PK * 2) + kb2);
                mma16816h(d[2 * g], ahr[k16], b);
                mma16816h(d[2 * g + 1], ahr[k16], b + 2);
            }
        }

        // ---- fold with x (LDG, L1-hot) ----
        if (DOUT == 32) {
            float xa0 = x0p[nc * 2], xa1 = x0p[nc * 2 + 1];
            float xb0 = x1p[nc * 2], xb1 = x1p[nc * 2 + 1];
#pragma unroll
            for (int n8 = 0; n8 < 8; n8++) {
                float xa = (n8 < 4) ? xa0 : xa1;
                float xb = (n8 < 4) ? xb0 : xb1;
                int slot = (n8 & 3) * 2;
                msg[0][slot]     += xa * d[n8][0];
                msg[0][slot + 1] += xa * d[n8][1];
                msg[1][slot]     += xb * d[n8][2];
                msg[1][slot + 1] += xb * d[n8][3];
            }
        } else {  // DOUT == 16: i = nc*4 + (n8>>1), o-slot = (n8&1)*2
#pragma unroll
            for (int n8 = 0; n8 < 8; n8++) {
                int i = nc * 4 + (n8 >> 1);
                float xa = x0p[i];
                float xb = x1p[i];
                int slot = (n8 & 1) * 2;
                msg[0][slot]     += xa * d[n8][0];
                msg[0][slot + 1] += xa * d[n8][1];
                msg[1][slot]     += xb * d[n8][2];
                msg[1][slot + 1] += xb * d[n8][3];
            }
        }

        if (++bidx == 3) bidx = 0;
    }

    // ---- scatter: single owner per (e,o); add per-node x@b2 term ----
    if (a0) {
        const float* tn = tnode + (long long)sv0 * DOUT;
        float* ap = agg + (long long)dv0 * DOUT;
#pragma unroll
        for (int s = 0; s < NO; s++) {
            int o = (s >> 1) * 8 + c2 + (s & 1);
            atomicAdd(ap + o, msg[0][s] + tn[o]);
        }
    }
    if (a1) {
        const float* tn = tnode + (long long)sv1 * DOUT;
        float* ap = agg + (long long)dv1 * DOUT;
#pragma unroll
        for (int s = 0; s < NO; s++) {
            int o = (s >> 1) * 8 + c2 + (s & 1);
            atomicAdd(ap + o, msg[1][s] + tn[o]);
        }
    }
}

// ---------------- node epilogue: mean + root GEMM + bias (+relu) ----------------
template <int DIN, int DOUT, bool MEAN, bool RELU>
__global__ __launch_bounds__(256)
void node_kernel(const float* __restrict__ xin, const float* __restrict__ agg,
                 const float* __restrict__ root, const float* __restrict__ bias,
                 const int* __restrict__ deg, float* __restrict__ out) {
    __shared__ float sroot[DIN * DOUT];
    __shared__ float sbias[DOUT];
    int tid = threadIdx.x;
    for (int i = tid; i < DIN * DOUT; i += 256) sroot[i] = root[i];
    if (tid < DOUT) sbias[tid] = bias[tid];
    __syncthreads();
    int idx = blockIdx.x * 256 + tid;
    if (idx >= KN * DOUT) return;
    int n = idx / DOUT, o = idx % DOUT;
    float v = agg[idx];
    if (MEAN) {
        int d = deg[n];
        v *= 1.f / (d > 0 ? (float)d : 1.f);
    }
    const float* xr = xin + n * DIN;
#pragma unroll
    for (int i = 0; i < DIN; i++) v = fmaf(xr[i], sroot[i * DOUT + o], v);
    v += sbias[o];
    if (RELU) v = fmaxf(v, 0.f);
    out[idx] = v;
}

// ---------------- launch ----------------
static constexpr int smem_mma() {
    return 128 * PK * 2 + 3 * (64 * PK * 2);  // 34816 + 52224 = 87040
}

extern "C" void kernel_launch(void* const* d_in, const int* in_sizes, int n_in,
                              void* d_out, int out_size) {
    const float* x = (const float*)d_in[0];
    const int* ei = (const int*)d_in[1];  // int32 (JAX x64-disabled downcast)
    const float* ea = (const float*)d_in[2];
    auto f = [&](int i) { return (const float*)d_in[i]; };
    float* out = (float*)d_out;
    const int* src = ei;
    const int* dstp = ei + KE;

    void *agg_p, *deg_p, *h1_p, *h2_p, *t_p, *wc1, *wc2, *wmu, *wlv;
    cudaGetSymbolAddress(&agg_p, g_agg);
    cudaGetSymbolAddress(&deg_p, g_deg);
    cudaGetSymbolAddress(&h1_p, g_h1);
    cudaGetSymbolAddress(&h2_p, g_h2);
    cudaGetSymbolAddress(&t_p, g_t);
    cudaGetSymbolAddress(&wc1, g_w2t_c1);
    cudaGetSymbolAddress(&wc2, g_w2t_c2);
    cudaGetSymbolAddress(&wmu, g_w2t_mu);
    cudaGetSymbolAddress(&wlv, g_w2t_lv);

    cudaFuncSetAttribute(edge_mma_kernel<16, 32>,
                         cudaFuncAttributeMaxDynamicSharedMemorySize, smem_mma());
    cudaFuncSetAttribute(edge_mma_kernel<32, 32>,
                         cudaFuncAttributeMaxDynamicSharedMemorySize, smem_mma());
    cudaFuncSetAttribute(edge_mma_kernel<32, 16>,
                         cudaFuncAttributeMaxDynamicSharedMemorySize, smem_mma());

    const int TB = (KE + 127) / 128;
    const int NB32 = (KN * 32 + 255) / 256;
    const int NB16 = (KN * 16 + 255) / 256;

    // prep w2 images (in-graph, deterministic)
    prep_w2_kernel<<<(512 * 128 + 255) / 256, 256>>>(f(5), 512, (uint8_t*)wc1);
    prep_w2_kernel<<<(1024 * 128 + 255) / 256, 256>>>(f(11), 1024, (uint8_t*)wc2);
    prep_w2_kernel<<<(512 * 128 + 255) / 256, 256>>>(f(17), 512, (uint8_t*)wmu);
    prep_w2_kernel<<<(512 * 128 + 255) / 256, 256>>>(f(23), 512, (uint8_t*)wlv);

    zero_i_kernel<<<(KN + 255) / 256, 256>>>((int*)deg_p, KN);
    deg_kernel<<<(KE + 255) / 256, 256>>>(dstp);

    // conv1: 16 -> 32, mean, relu  (xb2 also zeroes agg)
    xb2_kernel<16, 32><<<NB32, 256>>>(x, f(6), (float*)t_p, (float*)agg_p);
    edge_mma_kernel<16, 32><<<TB, 256, smem_mma()>>>(
        x, ea, src, dstp, f(3), f(4), (const uint8_t*)wc1, (const float*)t_p,
        (float*)agg_p);
    node_kernel<16, 32, true, true><<<NB32, 256>>>(
        x, (const float*)agg_p, f(7), f(8), (const int*)deg_p, (float*)h1_p);

    // conv2: 32 -> 32, mean, relu
    xb2_kernel<32, 32><<<NB32, 256>>>((const float*)h1_p, f(12), (float*)t_p,
                                      (float*)agg_p);
    edge_mma_kernel<32, 32><<<TB, 256, smem_mma()>>>(
        (const float*)h1_p, ea, src, dstp, f(9), f(10), (const uint8_t*)wc2,
        (const float*)t_p, (float*)agg_p);
    node_kernel<32, 32, true, true><<<NB32, 256>>>(
        (const float*)h1_p, (const float*)agg_p, f(13), f(14), (const int*)deg_p,
        (float*)h2_p);

    // mu: 32 -> 16, sum
    xb2_kernel<32, 16><<<NB16, 256>>>((const float*)h2_p, f(18), (float*)t_p,
                                      (float*)agg_p);
    edge_mma_kernel<32, 16><<<TB, 256, smem_mma()>>>(
        (const float*)h2_p, ea, src, dstp, f(15), f(16), (const uint8_t*)wmu,
        (const float*)t_p, (float*)agg_p);
    node_kernel<32, 16, false, false><<<NB16, 256>>>(
        (const float*)h2_p, (const float*)agg_p, f(19), f(20), (const int*)deg_p,
        out);

    // logvar: 32 -> 16, sum
    xb2_kernel<32, 16><<<NB16, 256>>>((const float*)h2_p, f(24), (float*)t_p,
                                      (float*)agg_p);
    edge_mma_kernel<32, 16><<<TB, 256, smem_mma()>>>(
        (const float*)h2_p, ea, src, dstp, f(21), f(22), (const uint8_t*)wlv,
        (const float*)t_p, (float*)agg_p);
    node_kernel<32, 16, false, false><<<NB16, 256>>>(
        (const float*)h2_p, (const float*)agg_p, f(25), f(26), (const int*)deg_p,
        out + KN * 16);
}